// round 1
// baseline (speedup 1.0000x reference)
#include <cuda_runtime.h>

#define EPSF 1e-5f
// Problem constants: B=8192, C=64, H=8, W=16, P=H*W=128, F5=8192

// ---------------- scratch (__device__ globals; no allocations) ----------------
__device__ float g_w2p[36864];      // conv2 weights repacked [(c*9+tap)][o]
__device__ float g_w3p[524288];     // lc3 weights [p][o][c]
__device__ float g_w4p[524288];     // lc4 weights [p][o][c]
__device__ float g_w5p[4194304];    // fc5 weights [n][p*64+c]
__device__ float g_a2[67108864];    // conv2 output, [p][b][c]   (268 MB)
__device__ float g_a4[67108864];    // lc4 output,   [b][p*64+c] (268 MB)
__device__ float g_a5[4194304];     // fc5 output [b][512]
__device__ float g_a6[4194304];     // fc6 output [b][512]
__device__ float g_a7[1048576];     // fc7 output [b][128]

// ---------------- weight prepacking (pure permutations) ----------------
__global__ void k_prep_w2(const float* __restrict__ w2) {
    int idx = blockIdx.x * 256 + threadIdx.x;            // 36864 total
    if (idx >= 36864) return;
    int o = idx / 576, r = idx % 576;                    // r = c*9+tap
    g_w2p[r * 64 + o] = w2[idx];
}

__global__ void k_prep_w34(const float* __restrict__ w3, const float* __restrict__ w4) {
    int idx = blockIdx.x * 256 + threadIdx.x;            // 2*524288 total
    int sel = idx >> 19;
    int i = idx & 524287;
    int o = i >> 13, c = (i >> 7) & 63, p = i & 127;     // in: [o][c][p]
    float v = sel ? w4[i] : w3[i];
    float* dst = sel ? g_w4p : g_w3p;
    dst[p * 4096 + o * 64 + c] = v;                      // out: [p][o][c]
}

__global__ void k_prep_w5(const float* __restrict__ w5) {
    int idx = blockIdx.x * 256 + threadIdx.x;            // 4194304 total
    int n = idx >> 13, k = idx & 8191;
    int c = k >> 7, p = k & 127;                         // k = c*128+p
    g_w5p[n * 8192 + p * 64 + c] = w5[idx];              // k' = p*64+c
}

// ---------------- fused front: bn0 + conv1 + bn1/relu + conv2 + bn2/relu ----------------
// One block per batch element. a1 kept in shared memory (padded 10x18 per channel).
__global__ __launch_bounds__(256) void k_front(
    const float* __restrict__ x,   const float* __restrict__ bn0,
    const float* __restrict__ w1,  const float* __restrict__ b1,
    const float* __restrict__ bn1, const float* __restrict__ b2,
    const float* __restrict__ bn2)
{
    __shared__ float h0s[180];          // padded 10x18, bn0 applied
    __shared__ float a1s[11520];        // 64 channels x padded 10x18
    int b = blockIdx.x;
    int t = threadIdx.x;

    for (int i = t; i < 180;   i += 256) h0s[i] = 0.f;
    for (int i = t; i < 11520; i += 256) a1s[i] = 0.f;
    __syncthreads();

    if (t < 128) {
        float s0 = bn0[0] * rsqrtf(bn0[3] + EPSF);
        float t0 = bn0[1] - bn0[2] * s0;
        int i = t >> 4, j = t & 15;                       // h[b,i,j] = x_flat[j*8+i]
        h0s[(i + 1) * 18 + (j + 1)] = x[b * 128 + j * 8 + i] * s0 + t0;
    }
    __syncthreads();

    // conv1 (1->64, 3x3 SAME) + bn1 + relu  -> a1s (padded per channel)
    for (int idx = t; idx < 8192; idx += 256) {
        int o = idx >> 7, p = idx & 127;
        int i = p >> 4, j = p & 15;
        float acc = 0.f;
        #pragma unroll
        for (int di = 0; di < 3; di++)
            #pragma unroll
            for (int dj = 0; dj < 3; dj++)
                acc = fmaf(h0s[(i + di) * 18 + (j + dj)], __ldg(&w1[o * 9 + di * 3 + dj]), acc);
        float s1 = bn1[o] * rsqrtf(bn1[192 + o] + EPSF);
        float t1 = bn1[64 + o] - bn1[128 + o] * s1;
        a1s[o * 180 + (i + 1) * 18 + (j + 1)] = fmaxf(fmaf(acc + b1[o], s1, t1), 0.f);
    }
    __syncthreads();

    // conv2 (64->64, 3x3 SAME) + bn2 + relu -> g_a2 [p][b][c]
    // thread: 4 output channels (oq*4..+3) x 8 pixels (pg + 16*px)
    int oq = t & 15, pg = t >> 4;
    float acc[8][4];
    #pragma unroll
    for (int px = 0; px < 8; px++)
        #pragma unroll
        for (int ci = 0; ci < 4; ci++) acc[px][ci] = 0.f;
    int pb[8];
    #pragma unroll
    for (int px = 0; px < 8; px++) {
        int p = pg + 16 * px;
        pb[px] = (p >> 4) * 18 + (p & 15);
    }
    const float4* w24 = reinterpret_cast<const float4*>(g_w2p);
    for (int c = 0; c < 64; c++) {
        const float* a1c = &a1s[c * 180];
        #pragma unroll
        for (int tap = 0; tap < 9; tap++) {
            float4 w = w24[(c * 9 + tap) * 16 + oq];       // L1-resident
            int off = (tap / 3) * 18 + (tap % 3);
            #pragma unroll
            for (int px = 0; px < 8; px++) {
                float a = a1c[pb[px] + off];
                acc[px][0] = fmaf(a, w.x, acc[px][0]);
                acc[px][1] = fmaf(a, w.y, acc[px][1]);
                acc[px][2] = fmaf(a, w.z, acc[px][2]);
                acc[px][3] = fmaf(a, w.w, acc[px][3]);
            }
        }
    }
    float s2[4], t2[4], bb[4];
    #pragma unroll
    for (int ci = 0; ci < 4; ci++) {
        int o = oq * 4 + ci;
        s2[ci] = bn2[o] * rsqrtf(bn2[192 + o] + EPSF);
        t2[ci] = bn2[64 + o] - bn2[128 + o] * s2[ci];
        bb[ci] = b2[o];
    }
    #pragma unroll
    for (int px = 0; px < 8; px++) {
        int p = pg + 16 * px;
        float4 v;
        v.x = fmaxf(fmaf(acc[px][0] + bb[0], s2[0], t2[0]), 0.f);
        v.y = fmaxf(fmaf(acc[px][1] + bb[1], s2[1], t2[1]), 0.f);
        v.z = fmaxf(fmaf(acc[px][2] + bb[2], s2[2], t2[2]), 0.f);
        v.w = fmaxf(fmaf(acc[px][3] + bb[3], s2[3], t2[3]), 0.f);
        *reinterpret_cast<float4*>(&g_a2[(size_t)p * 524288 + (size_t)b * 64 + oq * 4]) = v;
    }
}

// ---------------- fused lc3 + lc4 (per-pixel 64x64 channel mixing, chained) ----------------
// block: (batch-tile of 64, pixel p). Two back-to-back 64x64x64 GEMMs, intermediate in smem.
__global__ __launch_bounds__(256) void k_lc(const float* __restrict__ bn3,
                                            const float* __restrict__ bn4)
{
    __shared__ float As[64 * 65];
    __shared__ float Ws[64 * 65];
    int p  = blockIdx.y;
    int b0 = blockIdx.x * 64;
    int t  = threadIdx.x;

    for (int i = t; i < 4096; i += 256) {
        int r = i >> 6, c = i & 63;
        As[r * 65 + c] = g_a2[(size_t)p * 524288 + (size_t)(b0 + r) * 64 + c];
    }
    for (int i = t; i < 4096; i += 256)
        Ws[(i >> 6) * 65 + (i & 63)] = g_w3p[p * 4096 + i];
    __syncthreads();

    int tx = t & 15, ty = t >> 4;
    float acc[4][4];
    #pragma unroll
    for (int ri = 0; ri < 4; ri++)
        #pragma unroll
        for (int ci = 0; ci < 4; ci++) acc[ri][ci] = 0.f;

    for (int c = 0; c < 64; c++) {
        float a[4], w[4];
        #pragma unroll
        for (int ri = 0; ri < 4; ri++) a[ri] = As[(ty * 4 + ri) * 65 + c];
        #pragma unroll
        for (int ci = 0; ci < 4; ci++) w[ci] = Ws[(tx * 4 + ci) * 65 + c];
        #pragma unroll
        for (int ri = 0; ri < 4; ri++)
            #pragma unroll
            for (int ci = 0; ci < 4; ci++) acc[ri][ci] = fmaf(a[ri], w[ci], acc[ri][ci]);
    }
    float sv[4], tv[4];
    #pragma unroll
    for (int ci = 0; ci < 4; ci++) {
        int o = tx * 4 + ci;
        sv[ci] = bn3[o] * rsqrtf(bn3[192 + o] + EPSF);
        tv[ci] = bn3[64 + o] - bn3[128 + o] * sv[ci];
    }
    __syncthreads();   // all GEMM1 smem reads done
    #pragma unroll
    for (int ri = 0; ri < 4; ri++)
        #pragma unroll
        for (int ci = 0; ci < 4; ci++)
            As[(ty * 4 + ri) * 65 + tx * 4 + ci] = fmaxf(fmaf(acc[ri][ci], sv[ci], tv[ci]), 0.f);
    for (int i = t; i < 4096; i += 256)
        Ws[(i >> 6) * 65 + (i & 63)] = g_w4p[p * 4096 + i];
    __syncthreads();

    #pragma unroll
    for (int ri = 0; ri < 4; ri++)
        #pragma unroll
        for (int ci = 0; ci < 4; ci++) acc[ri][ci] = 0.f;
    for (int c = 0; c < 64; c++) {
        float a[4], w[4];
        #pragma unroll
        for (int ri = 0; ri < 4; ri++) a[ri] = As[(ty * 4 + ri) * 65 + c];
        #pragma unroll
        for (int ci = 0; ci < 4; ci++) w[ci] = Ws[(tx * 4 + ci) * 65 + c];
        #pragma unroll
        for (int ri = 0; ri < 4; ri++)
            #pragma unroll
            for (int ci = 0; ci < 4; ci++) acc[ri][ci] = fmaf(a[ri], w[ci], acc[ri][ci]);
    }
    #pragma unroll
    for (int ci = 0; ci < 4; ci++) {
        int o = tx * 4 + ci;
        sv[ci] = bn4[o] * rsqrtf(bn4[192 + o] + EPSF);
        tv[ci] = bn4[64 + o] - bn4[128 + o] * sv[ci];
    }
    #pragma unroll
    for (int ri = 0; ri < 4; ri++) {
        float4 v;
        v.x = fmaxf(fmaf(acc[ri][0], sv[0], tv[0]), 0.f);
        v.y = fmaxf(fmaf(acc[ri][1], sv[1], tv[1]), 0.f);
        v.z = fmaxf(fmaf(acc[ri][2], sv[2], tv[2]), 0.f);
        v.w = fmaxf(fmaf(acc[ri][3], sv[3], tv[3]), 0.f);
        *reinterpret_cast<float4*>(&g_a4[(size_t)(b0 + ty * 4 + ri) * 8192 + p * 64 + tx * 4]) = v;
    }
}

// ---------------- generic fp32 GEMM: out = act((A @ W^T + bias)*s + t) ----------------
// A[M,K] rm (scratch via asel), W[N,K] rm, scalar BN (bn ptr, (4,1)), relu flag.
__global__ __launch_bounds__(256) void k_gemm(
    int asel, int osel, int wsel,
    const float* __restrict__ Wext, const float* __restrict__ bias,
    const float* __restrict__ bn, int N, int K, int relu)
{
    const float* A  = (asel == 0) ? g_a4 : (asel == 1) ? g_a5 : g_a6;
    float*       Out = (osel == 0) ? g_a5 : (osel == 1) ? g_a6 : g_a7;
    const float* Wt = wsel ? g_w5p : Wext;

    __shared__ float As[128 * 33];
    __shared__ float Ws[64 * 33];
    int rb = blockIdx.x * 128;
    int nb = blockIdx.y * 64;
    int t = threadIdx.x;
    int tx = t & 15, ty = t >> 4;

    float acc[8][4];
    #pragma unroll
    for (int ri = 0; ri < 8; ri++)
        #pragma unroll
        for (int ci = 0; ci < 4; ci++) acc[ri][ci] = 0.f;

    for (int k0 = 0; k0 < K; k0 += 32) {
        for (int i = t; i < 4096; i += 256) {
            int r = i >> 5, c = i & 31;
            As[r * 33 + c] = A[(size_t)(rb + r) * K + k0 + c];
        }
        for (int i = t; i < 2048; i += 256) {
            int n = i >> 5, c = i & 31;
            Ws[n * 33 + c] = Wt[(size_t)(nb + n) * K + k0 + c];
        }
        __syncthreads();
        #pragma unroll 4
        for (int c = 0; c < 32; c++) {
            float a[8], w[4];
            #pragma unroll
            for (int ri = 0; ri < 8; ri++) a[ri] = As[(ty * 8 + ri) * 33 + c];
            #pragma unroll
            for (int ci = 0; ci < 4; ci++) w[ci] = Ws[(tx * 4 + ci) * 33 + c];
            #pragma unroll
            for (int ri = 0; ri < 8; ri++)
                #pragma unroll
                for (int ci = 0; ci < 4; ci++) acc[ri][ci] = fmaf(a[ri], w[ci], acc[ri][ci]);
        }
        __syncthreads();
    }
    float s = 1.f, tt = 0.f;
    if (bn) { s = bn[0] * rsqrtf(bn[3] + EPSF); tt = bn[1] - bn[2] * s; }
    float bv[4];
    #pragma unroll
    for (int ci = 0; ci < 4; ci++) bv[ci] = bias[nb + tx * 4 + ci];
    #pragma unroll
    for (int ri = 0; ri < 8; ri++) {
        float z[4];
        #pragma unroll
        for (int ci = 0; ci < 4; ci++) {
            z[ci] = fmaf(acc[ri][ci] + bv[ci], s, tt);
            if (relu) z[ci] = fmaxf(z[ci], 0.f);
        }
        float4 v = make_float4(z[0], z[1], z[2], z[3]);
        *reinterpret_cast<float4*>(&Out[(size_t)(rb + ty * 8 + ri) * N + nb + tx * 4]) = v;
    }
}

// ---------------- fc8: (B,128) @ (8,128)^T + b8 -> d_out ----------------
__global__ __launch_bounds__(256) void k_fc8(const float* __restrict__ w8,
                                             const float* __restrict__ b8,
                                             float* __restrict__ out)
{
    int t = threadIdx.x;
    int b = blockIdx.x * 32 + (t >> 3);
    int n = t & 7;
    const float* ar = &g_a7[b * 128];
    const float* wr = &w8[n * 128];
    float acc = 0.f;
    #pragma unroll 8
    for (int k = 0; k < 128; k++) acc = fmaf(ar[k], wr[k], acc);
    out[b * 8 + n] = acc + b8[n];
}

// ---------------- launch ----------------
extern "C" void kernel_launch(void* const* d_in, const int* in_sizes, int n_in,
                              void* d_out, int out_size)
{
    const float* x   = (const float*)d_in[0];
    const float* bn0 = (const float*)d_in[1];
    const float* w1  = (const float*)d_in[2];
    const float* b1  = (const float*)d_in[3];
    const float* bn1 = (const float*)d_in[4];
    const float* w2  = (const float*)d_in[5];
    const float* b2  = (const float*)d_in[6];
    const float* bn2 = (const float*)d_in[7];
    const float* w3  = (const float*)d_in[8];
    const float* bn3 = (const float*)d_in[9];
    const float* w4  = (const float*)d_in[10];
    const float* bn4 = (const float*)d_in[11];
    const float* w5  = (const float*)d_in[12];
    const float* b5  = (const float*)d_in[13];
    const float* bn5 = (const float*)d_in[14];
    const float* w6  = (const float*)d_in[15];
    const float* b6  = (const float*)d_in[16];
    const float* bn6 = (const float*)d_in[17];
    const float* w7  = (const float*)d_in[18];
    const float* b7  = (const float*)d_in[19];
    const float* bn7 = (const float*)d_in[20];
    const float* w8  = (const float*)d_in[21];
    const float* b8  = (const float*)d_in[22];
    float* out = (float*)d_out;

    k_prep_w2 <<<144,   256>>>(w2);
    k_prep_w34<<<4096,  256>>>(w3, w4);
    k_prep_w5 <<<16384, 256>>>(w5);

    k_front<<<8192, 256>>>(x, bn0, w1, b1, bn1, b2, bn2);          // bn0..conv2
    k_lc<<<dim3(128, 128), 256>>>(bn3, bn4);                        // lc3+lc4

    k_gemm<<<dim3(64, 8), 256>>>(0, 0, 1, nullptr, b5, bn5, 512, 8192, 1);  // fc5
    k_gemm<<<dim3(64, 8), 256>>>(1, 1, 0, w6,      b6, bn6, 512,  512, 1);  // fc6
    k_gemm<<<dim3(64, 2), 256>>>(2, 2, 0, w7,      b7, bn7, 128,  512, 1);  // fc7
    k_fc8<<<256, 256>>>(w8, b8, out);                                        // fc8
}

// round 2
// speedup vs baseline: 1.0052x; 1.0052x over previous
#include <cuda_runtime.h>

#define EPSF 1e-5f
// Problem constants: B=8192, C=64, H=8, W=16, P=H*W=128, F5=8192

// ---------------- scratch (__device__ globals; no allocations) ----------------
__device__ float g_w2p[36864];      // conv2 weights repacked [(c*9+tap)][o]
__device__ float g_w3p[524288];     // lc3 weights [p][o][c]
__device__ float g_w4p[524288];     // lc4 weights [p][o][c]
__device__ float g_w5p[4194304];    // fc5 weights [n][p*64+c]
__device__ float g_a2[67108864];    // conv2 output, [p][b][c]   (268 MB)
__device__ float g_a4[67108864];    // lc4 output,   [b][p*64+c] (268 MB)
__device__ float g_a5[4194304];     // fc5 output [b][512]
__device__ float g_a6[4194304];     // fc6 output [b][512]
__device__ float g_a7[1048576];     // fc7 output [b][128]

// ---------------- weight prepacking (pure permutations) ----------------
__global__ void k_prep_w2(const float* __restrict__ w2) {
    int idx = blockIdx.x * 256 + threadIdx.x;            // 36864 total
    if (idx >= 36864) return;
    int o = idx / 576, r = idx % 576;                    // r = c*9+tap
    g_w2p[r * 64 + o] = w2[idx];
}

__global__ void k_prep_w34(const float* __restrict__ w3, const float* __restrict__ w4) {
    int idx = blockIdx.x * 256 + threadIdx.x;            // 2*524288 total
    int sel = idx >> 19;
    int i = idx & 524287;
    int o = i >> 13, c = (i >> 7) & 63, p = i & 127;     // in: [o][c][p]
    float v = sel ? w4[i] : w3[i];
    float* dst = sel ? g_w4p : g_w3p;
    dst[p * 4096 + o * 64 + c] = v;                      // out: [p][o][c]
}

__global__ void k_prep_w5(const float* __restrict__ w5) {
    int idx = blockIdx.x * 256 + threadIdx.x;            // 4194304 total
    int n = idx >> 13, k = idx & 8191;
    int c = k >> 7, p = k & 127;                         // k = c*128+p
    g_w5p[n * 8192 + p * 64 + c] = w5[idx];              // k' = p*64+c
}

// ---------------- fused front: bn0 + conv1 + bn1/relu + conv2 + bn2/relu ----------------
// One block per batch element. a1 kept in shared memory (padded 10x18 per channel).
__global__ __launch_bounds__(256) void k_front(
    const float* __restrict__ x,   const float* __restrict__ bn0,
    const float* __restrict__ w1,  const float* __restrict__ b1,
    const float* __restrict__ bn1, const float* __restrict__ b2,
    const float* __restrict__ bn2)
{
    __shared__ float h0s[180];          // padded 10x18, bn0 applied
    __shared__ float a1s[11520];        // 64 channels x padded 10x18
    int b = blockIdx.x;
    int t = threadIdx.x;

    for (int i = t; i < 180;   i += 256) h0s[i] = 0.f;
    for (int i = t; i < 11520; i += 256) a1s[i] = 0.f;
    __syncthreads();

    if (t < 128) {
        float s0 = bn0[0] * rsqrtf(bn0[3] + EPSF);
        float t0 = bn0[1] - bn0[2] * s0;
        int i = t >> 4, j = t & 15;                       // h[b,i,j] = x_flat[j*8+i]
        h0s[(i + 1) * 18 + (j + 1)] = x[b * 128 + j * 8 + i] * s0 + t0;
    }
    __syncthreads();

    // conv1 (1->64, 3x3 SAME) + bn1 + relu  -> a1s (padded per channel)
    for (int idx = t; idx < 8192; idx += 256) {
        int o = idx >> 7, p = idx & 127;
        int i = p >> 4, j = p & 15;
        float acc = 0.f;
        #pragma unroll
        for (int di = 0; di < 3; di++)
            #pragma unroll
            for (int dj = 0; dj < 3; dj++)
                acc = fmaf(h0s[(i + di) * 18 + (j + dj)], __ldg(&w1[o * 9 + di * 3 + dj]), acc);
        float s1 = bn1[o] * rsqrtf(bn1[192 + o] + EPSF);
        float t1 = bn1[64 + o] - bn1[128 + o] * s1;
        a1s[o * 180 + (i + 1) * 18 + (j + 1)] = fmaxf(fmaf(acc + b1[o], s1, t1), 0.f);
    }
    __syncthreads();

    // conv2 (64->64, 3x3 SAME) + bn2 + relu -> g_a2 [p][b][c]
    // thread: 4 output channels (oq*4..+3) x 8 pixels (pg + 16*px)
    int oq = t & 15, pg = t >> 4;
    float acc[8][4];
    #pragma unroll
    for (int px = 0; px < 8; px++)
        #pragma unroll
        for (int ci = 0; ci < 4; ci++) acc[px][ci] = 0.f;
    int pb[8];
    #pragma unroll
    for (int px = 0; px < 8; px++) {
        int p = pg + 16 * px;
        pb[px] = (p >> 4) * 18 + (p & 15);
    }
    const float4* w24 = reinterpret_cast<const float4*>(g_w2p);
    for (int c = 0; c < 64; c++) {
        const float* a1c = &a1s[c * 180];
        #pragma unroll
        for (int tap = 0; tap < 9; tap++) {
            float4 w = w24[(c * 9 + tap) * 16 + oq];       // L1-resident
            int off = (tap / 3) * 18 + (tap % 3);
            #pragma unroll
            for (int px = 0; px < 8; px++) {
                float a = a1c[pb[px] + off];
                acc[px][0] = fmaf(a, w.x, acc[px][0]);
                acc[px][1] = fmaf(a, w.y, acc[px][1]);
                acc[px][2] = fmaf(a, w.z, acc[px][2]);
                acc[px][3] = fmaf(a, w.w, acc[px][3]);
            }
        }
    }
    float s2[4], t2[4], bb[4];
    #pragma unroll
    for (int ci = 0; ci < 4; ci++) {
        int o = oq * 4 + ci;
        s2[ci] = bn2[o] * rsqrtf(bn2[192 + o] + EPSF);
        t2[ci] = bn2[64 + o] - bn2[128 + o] * s2[ci];
        bb[ci] = b2[o];
    }
    #pragma unroll
    for (int px = 0; px < 8; px++) {
        int p = pg + 16 * px;
        float4 v;
        v.x = fmaxf(fmaf(acc[px][0] + bb[0], s2[0], t2[0]), 0.f);
        v.y = fmaxf(fmaf(acc[px][1] + bb[1], s2[1], t2[1]), 0.f);
        v.z = fmaxf(fmaf(acc[px][2] + bb[2], s2[2], t2[2]), 0.f);
        v.w = fmaxf(fmaf(acc[px][3] + bb[3], s2[3], t2[3]), 0.f);
        *reinterpret_cast<float4*>(&g_a2[(size_t)p * 524288 + (size_t)b * 64 + oq * 4]) = v;
    }
}

// ---------------- fused lc3 + lc4 (per-pixel 64x64 channel mixing, chained) ----------------
// block: (batch-tile of 64, pixel p). Two back-to-back 64x64x64 GEMMs, intermediate in smem.
__global__ __launch_bounds__(256) void k_lc(const float* __restrict__ bn3,
                                            const float* __restrict__ bn4)
{
    __shared__ float As[64 * 65];
    __shared__ float Ws[64 * 65];
    int p  = blockIdx.y;
    int b0 = blockIdx.x * 64;
    int t  = threadIdx.x;

    for (int i = t; i < 4096; i += 256) {
        int r = i >> 6, c = i & 63;
        As[r * 65 + c] = g_a2[(size_t)p * 524288 + (size_t)(b0 + r) * 64 + c];
    }
    for (int i = t; i < 4096; i += 256)
        Ws[(i >> 6) * 65 + (i & 63)] = g_w3p[p * 4096 + i];
    __syncthreads();

    int tx = t & 15, ty = t >> 4;
    float acc[4][4];
    #pragma unroll
    for (int ri = 0; ri < 4; ri++)
        #pragma unroll
        for (int ci = 0; ci < 4; ci++) acc[ri][ci] = 0.f;

    for (int c = 0; c < 64; c++) {
        float a[4], w[4];
        #pragma unroll
        for (int ri = 0; ri < 4; ri++) a[ri] = As[(ty * 4 + ri) * 65 + c];
        #pragma unroll
        for (int ci = 0; ci < 4; ci++) w[ci] = Ws[(tx * 4 + ci) * 65 + c];
        #pragma unroll
        for (int ri = 0; ri < 4; ri++)
            #pragma unroll
            for (int ci = 0; ci < 4; ci++) acc[ri][ci] = fmaf(a[ri], w[ci], acc[ri][ci]);
    }
    float sv[4], tv[4];
    #pragma unroll
    for (int ci = 0; ci < 4; ci++) {
        int o = tx * 4 + ci;
        sv[ci] = bn3[o] * rsqrtf(bn3[192 + o] + EPSF);
        tv[ci] = bn3[64 + o] - bn3[128 + o] * sv[ci];
    }
    __syncthreads();   // all GEMM1 smem reads done
    #pragma unroll
    for (int ri = 0; ri < 4; ri++)
        #pragma unroll
        for (int ci = 0; ci < 4; ci++)
            As[(ty * 4 + ri) * 65 + tx * 4 + ci] = fmaxf(fmaf(acc[ri][ci], sv[ci], tv[ci]), 0.f);
    for (int i = t; i < 4096; i += 256)
        Ws[(i >> 6) * 65 + (i & 63)] = g_w4p[p * 4096 + i];
    __syncthreads();

    #pragma unroll
    for (int ri = 0; ri < 4; ri++)
        #pragma unroll
        for (int ci = 0; ci < 4; ci++) acc[ri][ci] = 0.f;
    for (int c = 0; c < 64; c++) {
        float a[4], w[4];
        #pragma unroll
        for (int ri = 0; ri < 4; ri++) a[ri] = As[(ty * 4 + ri) * 65 + c];
        #pragma unroll
        for (int ci = 0; ci < 4; ci++) w[ci] = Ws[(tx * 4 + ci) * 65 + c];
        #pragma unroll
        for (int ri = 0; ri < 4; ri++)
            #pragma unroll
            for (int ci = 0; ci < 4; ci++) acc[ri][ci] = fmaf(a[ri], w[ci], acc[ri][ci]);
    }
    #pragma unroll
    for (int ci = 0; ci < 4; ci++) {
        int o = tx * 4 + ci;
        sv[ci] = bn4[o] * rsqrtf(bn4[192 + o] + EPSF);
        tv[ci] = bn4[64 + o] - bn4[128 + o] * sv[ci];
    }
    #pragma unroll
    for (int ri = 0; ri < 4; ri++) {
        float4 v;
        v.x = fmaxf(fmaf(acc[ri][0], sv[0], tv[0]), 0.f);
        v.y = fmaxf(fmaf(acc[ri][1], sv[1], tv[1]), 0.f);
        v.z = fmaxf(fmaf(acc[ri][2], sv[2], tv[2]), 0.f);
        v.w = fmaxf(fmaf(acc[ri][3], sv[3], tv[3]), 0.f);
        *reinterpret_cast<float4*>(&g_a4[(size_t)(b0 + ty * 4 + ri) * 8192 + p * 64 + tx * 4]) = v;
    }
}

// ---------------- generic fp32 GEMM: out = act((A @ W^T + bias)*s + t) ----------------
// A[M,K] rm (scratch via asel), W[N,K] rm, scalar BN (bn ptr, (4,1)), relu flag.
__global__ __launch_bounds__(256) void k_gemm(
    int asel, int osel, int wsel,
    const float* __restrict__ Wext, const float* __restrict__ bias,
    const float* __restrict__ bn, int N, int K, int relu)
{
    const float* A  = (asel == 0) ? g_a4 : (asel == 1) ? g_a5 : g_a6;
    float*       Out = (osel == 0) ? g_a5 : (osel == 1) ? g_a6 : g_a7;
    const float* Wt = wsel ? g_w5p : Wext;

    __shared__ float As[128 * 33];
    __shared__ float Ws[64 * 33];
    int rb = blockIdx.x * 128;
    int nb = blockIdx.y * 64;
    int t = threadIdx.x;
    int tx = t & 15, ty = t >> 4;

    float acc[8][4];
    #pragma unroll
    for (int ri = 0; ri < 8; ri++)
        #pragma unroll
        for (int ci = 0; ci < 4; ci++) acc[ri][ci] = 0.f;

    for (int k0 = 0; k0 < K; k0 += 32) {
        for (int i = t; i < 4096; i += 256) {
            int r = i >> 5, c = i & 31;
            As[r * 33 + c] = A[(size_t)(rb + r) * K + k0 + c];
        }
        for (int i = t; i < 2048; i += 256) {
            int n = i >> 5, c = i & 31;
            Ws[n * 33 + c] = Wt[(size_t)(nb + n) * K + k0 + c];
        }
        __syncthreads();
        #pragma unroll 4
        for (int c = 0; c < 32; c++) {
            float a[8], w[4];
            #pragma unroll
            for (int ri = 0; ri < 8; ri++) a[ri] = As[(ty * 8 + ri) * 33 + c];
            #pragma unroll
            for (int ci = 0; ci < 4; ci++) w[ci] = Ws[(tx * 4 + ci) * 33 + c];
            #pragma unroll
            for (int ri = 0; ri < 8; ri++)
                #pragma unroll
                for (int ci = 0; ci < 4; ci++) acc[ri][ci] = fmaf(a[ri], w[ci], acc[ri][ci]);
        }
        __syncthreads();
    }
    float s = 1.f, tt = 0.f;
    if (bn) { s = bn[0] * rsqrtf(bn[3] + EPSF); tt = bn[1] - bn[2] * s; }
    float bv[4];
    #pragma unroll
    for (int ci = 0; ci < 4; ci++) bv[ci] = bias[nb + tx * 4 + ci];
    #pragma unroll
    for (int ri = 0; ri < 8; ri++) {
        float z[4];
        #pragma unroll
        for (int ci = 0; ci < 4; ci++) {
            z[ci] = fmaf(acc[ri][ci] + bv[ci], s, tt);
            if (relu) z[ci] = fmaxf(z[ci], 0.f);
        }
        float4 v = make_float4(z[0], z[1], z[2], z[3]);
        *reinterpret_cast<float4*>(&Out[(size_t)(rb + ty * 8 + ri) * N + nb + tx * 4]) = v;
    }
}

// ---------------- fc8: (B,128) @ (8,128)^T + b8 -> d_out ----------------
__global__ __launch_bounds__(256) void k_fc8(const float* __restrict__ w8,
                                             const float* __restrict__ b8,
                                             float* __restrict__ out)
{
    int t = threadIdx.x;
    int b = blockIdx.x * 32 + (t >> 3);
    int n = t & 7;
    const float* ar = &g_a7[b * 128];
    const float* wr = &w8[n * 128];
    float acc = 0.f;
    #pragma unroll 8
    for (int k = 0; k < 128; k++) acc = fmaf(ar[k], wr[k], acc);
    out[b * 8 + n] = acc + b8[n];
}

// ---------------- launch ----------------
extern "C" void kernel_launch(void* const* d_in, const int* in_sizes, int n_in,
                              void* d_out, int out_size)
{
    const float* x   = (const float*)d_in[0];
    const float* bn0 = (const float*)d_in[1];
    const float* w1  = (const float*)d_in[2];
    const float* b1  = (const float*)d_in[3];
    const float* bn1 = (const float*)d_in[4];
    const float* w2  = (const float*)d_in[5];
    const float* b2  = (const float*)d_in[6];
    const float* bn2 = (const float*)d_in[7];
    const float* w3  = (const float*)d_in[8];
    const float* bn3 = (const float*)d_in[9];
    const float* w4  = (const float*)d_in[10];
    const float* bn4 = (const float*)d_in[11];
    const float* w5  = (const float*)d_in[12];
    const float* b5  = (const float*)d_in[13];
    const float* bn5 = (const float*)d_in[14];
    const float* w6  = (const float*)d_in[15];
    const float* b6  = (const float*)d_in[16];
    const float* bn6 = (const float*)d_in[17];
    const float* w7  = (const float*)d_in[18];
    const float* b7  = (const float*)d_in[19];
    const float* bn7 = (const float*)d_in[20];
    const float* w8  = (const float*)d_in[21];
    const float* b8  = (const float*)d_in[22];
    float* out = (float*)d_out;

    k_prep_w2 <<<144,   256>>>(w2);
    k_prep_w34<<<4096,  256>>>(w3, w4);
    k_prep_w5 <<<16384, 256>>>(w5);

    k_front<<<8192, 256>>>(x, bn0, w1, b1, bn1, b2, bn2);          // bn0..conv2
    k_lc<<<dim3(128, 128), 256>>>(bn3, bn4);                        // lc3+lc4

    k_gemm<<<dim3(64, 8), 256>>>(0, 0, 1, nullptr, b5, bn5, 512, 8192, 1);  // fc5
    k_gemm<<<dim3(64, 8), 256>>>(1, 1, 0, w6,      b6, bn6, 512,  512, 1);  // fc6
    k_gemm<<<dim3(64, 2), 256>>>(2, 2, 0, w7,      b7, bn7, 128,  512, 1);  // fc7
    k_fc8<<<256, 256>>>(w8, b8, out);                                        // fc8
}

// round 5
// speedup vs baseline: 1.5947x; 1.5865x over previous
#include <cuda_runtime.h>
#include <cuda_fp16.h>
#include <mma.h>
#include <cstdint>
using namespace nvcuda;
#define EPSF 1e-5f
// B=8192, C=64, H=8, W=16, P=128, F5=8192

// ---------------- scratch ----------------
__device__ float  g_w2p[36864];                         // conv2 w [(c*9+tap)][o] fp32
__device__ __half g_w3h[524288], g_w3l[524288];         // lc3 w [p][o][c] hi/lo
__device__ __half g_w4h[524288], g_w4l[524288];         // lc4 w [p][o][c] hi/lo
__device__ __half g_w5h[4194304], g_w5l[4194304];       // fc5 w [n][p*64+c] hi/lo
__device__ __half g_a2h[67108864], g_a2l[67108864];     // conv2 out [p][b][c] hi/lo
__device__ __half g_a4h[67108864], g_a4l[67108864];     // lc4 out [b][p*64+c] hi/lo
__device__ float  g_a5[4194304], g_a6[4194304], g_a7[1048576];

__device__ __forceinline__ uint32_t packh2(__half a, __half b) {
    __half2 h = __halves2half2(a, b);
    return *reinterpret_cast<uint32_t*>(&h);
}
// load [rows x 64 halves] tile into smem rows of 72 halves (pad)
__device__ __forceinline__ void ldt(const __half* __restrict__ src, size_t rowStride,
                                    __half* dst, int t, int nt, int rows) {
    for (int i = t; i < rows * 8; i += nt) {
        int r = i >> 3, c = i & 7;
        *reinterpret_cast<uint4*>(&dst[r * 72 + c * 8]) =
            *reinterpret_cast<const uint4*>(&src[(size_t)r * rowStride + c * 8]);
    }
}

// ---------------- weight prep ----------------
__global__ void k_prep_w2(const float* __restrict__ w2) {
    int idx = blockIdx.x * 256 + threadIdx.x;
    if (idx >= 36864) return;
    int o = idx / 576, r = idx % 576;
    g_w2p[r * 64 + o] = w2[idx];
}
__global__ void k_prep_w34(const float* __restrict__ w3, const float* __restrict__ w4) {
    int idx = blockIdx.x * 256 + threadIdx.x;            // 1048576
    int sel = idx >> 19, i = idx & 524287;
    int o = i >> 13, c = (i >> 7) & 63, p = i & 127;
    float v = sel ? w4[i] : w3[i];
    __half h = __float2half_rn(v), l = __float2half_rn(v - __half2float(h));
    int d = p * 4096 + o * 64 + c;
    if (sel) { g_w4h[d] = h; g_w4l[d] = l; } else { g_w3h[d] = h; g_w3l[d] = l; }
}
__global__ void k_prep_w5(const float* __restrict__ w5) {
    int idx = blockIdx.x * 256 + threadIdx.x;            // 4194304
    int n = idx >> 13, k = idx & 8191;
    int c = k >> 7, p = k & 127;
    float v = w5[idx];
    __half h = __float2half_rn(v);
    int d = n * 8192 + p * 64 + c;
    g_w5h[d] = h; g_w5l[d] = __float2half_rn(v - __half2float(h));
}

// ---------------- front: bn0+conv1+bn1/relu+conv2+bn2/relu (fp32) -> hi/lo halves ----------------
__global__ __launch_bounds__(256) void k_front(
    const float* __restrict__ x, const float* __restrict__ bn0,
    const float* __restrict__ w1, const float* __restrict__ b1,
    const float* __restrict__ bn1, const float* __restrict__ b2,
    const float* __restrict__ bn2)
{
    __shared__ float h0s[180];
    __shared__ float a1s[11520];
    int b = blockIdx.x, t = threadIdx.x;
    for (int i = t; i < 180;   i += 256) h0s[i] = 0.f;
    for (int i = t; i < 11520; i += 256) a1s[i] = 0.f;
    __syncthreads();
    if (t < 128) {
        float s0 = bn0[0] * rsqrtf(bn0[3] + EPSF);
        float t0 = bn0[1] - bn0[2] * s0;
        int i = t >> 4, j = t & 15;
        h0s[(i + 1) * 18 + (j + 1)] = x[b * 128 + j * 8 + i] * s0 + t0;
    }
    __syncthreads();
    for (int idx = t; idx < 8192; idx += 256) {
        int o = idx >> 7, p = idx & 127;
        int i = p >> 4, j = p & 15;
        float acc = 0.f;
        #pragma unroll
        for (int di = 0; di < 3; di++)
            #pragma unroll
            for (int dj = 0; dj < 3; dj++)
                acc = fmaf(h0s[(i + di) * 18 + (j + dj)], __ldg(&w1[o * 9 + di * 3 + dj]), acc);
        float s1 = bn1[o] * rsqrtf(bn1[192 + o] + EPSF);
        float t1 = bn1[64 + o] - bn1[128 + o] * s1;
        a1s[o * 180 + (i + 1) * 18 + (j + 1)] = fmaxf(fmaf(acc + b1[o], s1, t1), 0.f);
    }
    __syncthreads();
    int oq = t & 15, pg = t >> 4;
    float acc[8][4];
    #pragma unroll
    for (int px = 0; px < 8; px++)
        #pragma unroll
        for (int ci = 0; ci < 4; ci++) acc[px][ci] = 0.f;
    int pb[8];
    #pragma unroll
    for (int px = 0; px < 8; px++) {
        int p = pg + 16 * px;
        pb[px] = (p >> 4) * 18 + (p & 15);
    }
    const float4* w24 = reinterpret_cast<const float4*>(g_w2p);
    for (int c = 0; c < 64; c++) {
        const float* a1c = &a1s[c * 180];
        #pragma unroll
        for (int tap = 0; tap < 9; tap++) {
            float4 w = w24[(c * 9 + tap) * 16 + oq];
            int off = (tap / 3) * 18 + (tap % 3);
            #pragma unroll
            for (int px = 0; px < 8; px++) {
                float a = a1c[pb[px] + off];
                acc[px][0] = fmaf(a, w.x, acc[px][0]);
                acc[px][1] = fmaf(a, w.y, acc[px][1]);
                acc[px][2] = fmaf(a, w.z, acc[px][2]);
                acc[px][3] = fmaf(a, w.w, acc[px][3]);
            }
        }
    }
    float s2[4], t2[4], bb[4];
    #pragma unroll
    for (int ci = 0; ci < 4; ci++) {
        int o = oq * 4 + ci;
        s2[ci] = bn2[o] * rsqrtf(bn2[192 + o] + EPSF);
        t2[ci] = bn2[64 + o] - bn2[128 + o] * s2[ci];
        bb[ci] = b2[o];
    }
    #pragma unroll
    for (int px = 0; px < 8; px++) {
        int p = pg + 16 * px;
        float z[4]; __half hh[4];
        #pragma unroll
        for (int ci = 0; ci < 4; ci++) {
            z[ci] = fmaxf(fmaf(acc[px][ci] + bb[ci], s2[ci], t2[ci]), 0.f);
            hh[ci] = __float2half_rn(z[ci]);
        }
        uint2 hv = make_uint2(packh2(hh[0], hh[1]), packh2(hh[2], hh[3]));
        uint2 lv = make_uint2(
            packh2(__float2half_rn(z[0] - __half2float(hh[0])), __float2half_rn(z[1] - __half2float(hh[1]))),
            packh2(__float2half_rn(z[2] - __half2float(hh[2])), __float2half_rn(z[3] - __half2float(hh[3]))));
        size_t o4 = (size_t)p * 524288 + (size_t)b * 64 + oq * 4;
        *reinterpret_cast<uint2*>(&g_a2h[o4]) = hv;
        *reinterpret_cast<uint2*>(&g_a2l[o4]) = lv;
    }
}

// ---------------- lc3+lc4 via wmma fp16x3, chained in smem ----------------
// grid (64 batch-tiles of 128, 128 pixels), 256 threads (8 warps, warp tile 32x32).
// smem bytes: AH 0, AL 18432, W3H 36864, W3L 46080, W4H 55296, W4L 64512,
//             XH 73728, XL 92160, BN 110592 (s3,t3,s4,t4: 4x64 f32) -> 111616 total
#define LC_SMEM 111616
typedef wmma::fragment<wmma::matrix_a, 16,16,16, __half, wmma::row_major> FragA;
typedef wmma::fragment<wmma::matrix_b, 16,16,16, __half, wmma::col_major> FragB;
typedef wmma::fragment<wmma::accumulator, 16,16,16, float> FragC;

__global__ __launch_bounds__(256) void k_lc_tc(const float* __restrict__ bn3,
                                               const float* __restrict__ bn4)
{
    extern __shared__ __align__(16) char smem[];
    __half* AH  = reinterpret_cast<__half*>(smem);
    __half* AL  = reinterpret_cast<__half*>(smem + 18432);
    __half* W3H = reinterpret_cast<__half*>(smem + 36864);
    __half* W3L = reinterpret_cast<__half*>(smem + 46080);
    __half* W4H = reinterpret_cast<__half*>(smem + 55296);
    __half* W4L = reinterpret_cast<__half*>(smem + 64512);
    __half* XH  = reinterpret_cast<__half*>(smem + 73728);
    __half* XL  = reinterpret_cast<__half*>(smem + 92160);
    float*  BN  = reinterpret_cast<float*>(smem + 110592);   // s3|t3|s4|t4
    float*  FB  = reinterpret_cast<float*>(smem);            // f32 out buf [128][68], aliases AH/AL

    int p = blockIdx.y, b0 = blockIdx.x * 128, t = threadIdx.x;
    int w = t >> 5, wm = w & 3, wn = w >> 2;

    if (t < 64) {
        float s = bn3[t] * rsqrtf(bn3[192 + t] + EPSF);
        BN[t] = s; BN[64 + t] = bn3[64 + t] - bn3[128 + t] * s;
        s = bn4[t] * rsqrtf(bn4[192 + t] + EPSF);
        BN[128 + t] = s; BN[192 + t] = bn4[64 + t] - bn4[128 + t] * s;
    }
    size_t ab = (size_t)p * 524288 + (size_t)b0 * 64;
    ldt(g_a2h + ab, 64, AH, t, 256, 128);
    ldt(g_a2l + ab, 64, AL, t, 256, 128);
    ldt(g_w3h + p * 4096, 64, W3H, t, 256, 64);
    ldt(g_w3l + p * 4096, 64, W3L, t, 256, 64);
    ldt(g_w4h + p * 4096, 64, W4H, t, 256, 64);
    ldt(g_w4l + p * 4096, 64, W4L, t, 256, 64);
    __syncthreads();

    FragC acc[2][2];
    FragA ah, al;
    FragB bh, bl;
    #pragma unroll
    for (int mt = 0; mt < 2; mt++)
        #pragma unroll
        for (int nt = 0; nt < 2; nt++) wmma::fill_fragment(acc[mt][nt], 0.f);
    #pragma unroll
    for (int ks = 0; ks < 4; ks++) {
        #pragma unroll
        for (int mt = 0; mt < 2; mt++) {
            wmma::load_matrix_sync(ah, &AH[(wm * 32 + mt * 16) * 72 + ks * 16], 72);
            wmma::load_matrix_sync(al, &AL[(wm * 32 + mt * 16) * 72 + ks * 16], 72);
            #pragma unroll
            for (int nt = 0; nt < 2; nt++) {
                wmma::load_matrix_sync(bh, &W3H[(wn * 32 + nt * 16) * 72 + ks * 16], 72);
                wmma::load_matrix_sync(bl, &W3L[(wn * 32 + nt * 16) * 72 + ks * 16], 72);
                wmma::mma_sync(acc[mt][nt], ah, bh, acc[mt][nt]);
                wmma::mma_sync(acc[mt][nt], al, bh, acc[mt][nt]);
                wmma::mma_sync(acc[mt][nt], ah, bl, acc[mt][nt]);
            }
        }
    }
    __syncthreads();   // done reading AH/AL
    #pragma unroll
    for (int mt = 0; mt < 2; mt++)
        #pragma unroll
        for (int nt = 0; nt < 2; nt++)
            wmma::store_matrix_sync(&FB[(wm * 32 + mt * 16) * 68 + wn * 32 + nt * 16],
                                    acc[mt][nt], 68, wmma::mem_row_major);
    __syncthreads();
    // epilogue1: bn3+relu -> hi/lo X
    for (int j = 0; j < 8; j++) {
        int g = t + j * 256;                 // 2048 groups of 4 cols
        int r = g >> 4, c4 = (g & 15) * 4;
        float4 v = *reinterpret_cast<float4*>(&FB[r * 68 + c4]);
        float z[4]; __half hh[4];
        float* vp = &v.x;
        #pragma unroll
        for (int q = 0; q < 4; q++) {
            z[q] = fmaxf(fmaf(vp[q], BN[c4 + q], BN[64 + c4 + q]), 0.f);
            hh[q] = __float2half_rn(z[q]);
        }
        *reinterpret_cast<uint32_t*>(&XH[r * 72 + c4])     = packh2(hh[0], hh[1]);
        *reinterpret_cast<uint32_t*>(&XH[r * 72 + c4 + 2]) = packh2(hh[2], hh[3]);
        *reinterpret_cast<uint32_t*>(&XL[r * 72 + c4]) =
            packh2(__float2half_rn(z[0] - __half2float(hh[0])), __float2half_rn(z[1] - __half2float(hh[1])));
        *reinterpret_cast<uint32_t*>(&XL[r * 72 + c4 + 2]) =
            packh2(__float2half_rn(z[2] - __half2float(hh[2])), __float2half_rn(z[3] - __half2float(hh[3])));
    }
    __syncthreads();
    // GEMM2
    #pragma unroll
    for (int mt = 0; mt < 2; mt++)
        #pragma unroll
        for (int nt = 0; nt < 2; nt++) wmma::fill_fragment(acc[mt][nt], 0.f);
    #pragma unroll
    for (int ks = 0; ks < 4; ks++) {
        #pragma unroll
        for (int mt = 0; mt < 2; mt++) {
            wmma::load_matrix_sync(ah, &XH[(wm * 32 + mt * 16) * 72 + ks * 16], 72);
            wmma::load_matrix_sync(al, &XL[(wm * 32 + mt * 16) * 72 + ks * 16], 72);
            #pragma unroll
            for (int nt = 0; nt < 2; nt++) {
                wmma::load_matrix_sync(bh, &W4H[(wn * 32 + nt * 16) * 72 + ks * 16], 72);
                wmma::load_matrix_sync(bl, &W4L[(wn * 32 + nt * 16) * 72 + ks * 16], 72);
                wmma::mma_sync(acc[mt][nt], ah, bh, acc[mt][nt]);
                wmma::mma_sync(acc[mt][nt], al, bh, acc[mt][nt]);
                wmma::mma_sync(acc[mt][nt], ah, bl, acc[mt][nt]);
            }
        }
    }
    __syncthreads();
    #pragma unroll
    for (int mt = 0; mt < 2; mt++)
        #pragma unroll
        for (int nt = 0; nt < 2; nt++)
            wmma::store_matrix_sync(&FB[(wm * 32 + mt * 16) * 68 + wn * 32 + nt * 16],
                                    acc[mt][nt], 68, wmma::mem_row_major);
    __syncthreads();
    // epilogue2: bn4+relu -> g_a4 hi/lo
    for (int j = 0; j < 8; j++) {
        int g = t + j * 256;
        int r = g >> 4, c4 = (g & 15) * 4;
        float4 v = *reinterpret_cast<float4*>(&FB[r * 68 + c4]);
        float z[4]; __half hh[4];
        float* vp = &v.x;
        #pragma unroll
        for (int q = 0; q < 4; q++) {
            z[q] = fmaxf(fmaf(vp[q], BN[128 + c4 + q], BN[192 + c4 + q]), 0.f);
            hh[q] = __float2half_rn(z[q]);
        }
        size_t o2 = (size_t)(b0 + r) * 8192 + p * 64 + c4;
        *reinterpret_cast<uint2*>(&g_a4h[o2]) =
            make_uint2(packh2(hh[0], hh[1]), packh2(hh[2], hh[3]));
        *reinterpret_cast<uint2*>(&g_a4l[o2]) = make_uint2(
            packh2(__float2half_rn(z[0] - __half2float(hh[0])), __float2half_rn(z[1] - __half2float(hh[1]))),
            packh2(__float2half_rn(z[2] - __half2float(hh[2])), __float2half_rn(z[3] - __half2float(hh[3]))));
    }
}

// ---------------- fc5 via wmma fp16x3: (8192x8192)@(512x8192)^T ----------------
// grid (64, 4), 256 threads (8 warps), CTA tile 128x128, warp tile 32x64.
// smem: AH 0 (18432), AL 18432, WH 36864 (18432), WL 55296 -> 73728; f32 out aliases 0 ([128][132])
#define F5_SMEM 73728
__global__ __launch_bounds__(256) void k_fc5_tc(const float* __restrict__ b5,
                                                const float* __restrict__ bn5)
{
    extern __shared__ __align__(16) char smem[];
    __half* AH = reinterpret_cast<__half*>(smem);
    __half* AL = reinterpret_cast<__half*>(smem + 18432);
    __half* WH = reinterpret_cast<__half*>(smem + 36864);
    __half* WL = reinterpret_cast<__half*>(smem + 55296);
    float*  FB = reinterpret_cast<float*>(smem);            // [128][132]

    int b0 = blockIdx.x * 128, nb = blockIdx.y * 128, t = threadIdx.x;
    int w = t >> 5, wm = w & 3, wn = w >> 2;

    FragC acc[2][4];
    FragA ah, al;
    FragB bh, bl;
    #pragma unroll
    for (int mt = 0; mt < 2; mt++)
        #pragma unroll
        for (int nt = 0; nt < 4; nt++) wmma::fill_fragment(acc[mt][nt], 0.f);

    for (int k = 0; k < 128; k++) {
        ldt(g_a4h + (size_t)b0 * 8192 + k * 64, 8192, AH, t, 256, 128);
        ldt(g_a4l + (size_t)b0 * 8192 + k * 64, 8192, AL, t, 256, 128);
        ldt(g_w5h + (size_t)nb * 8192 + k * 64, 8192, WH, t, 256, 128);
        ldt(g_w5l + (size_t)nb * 8192 + k * 64, 8192, WL, t, 256, 128);
        __syncthreads();
        #pragma unroll
        for (int ks = 0; ks < 4; ks++) {
            #pragma unroll
            for (int mt = 0; mt < 2; mt++) {
                wmma::load_matrix_sync(ah, &AH[(wm * 32 + mt * 16) * 72 + ks * 16], 72);
                wmma::load_matrix_sync(al, &AL[(wm * 32 + mt * 16) * 72 + ks * 16], 72);
                #pragma unroll
                for (int nt = 0; nt < 4; nt++) {
                    wmma::load_matrix_sync(bh, &WH[(wn * 64 + nt * 16) * 72 + ks * 16], 72);
                    wmma::load_matrix_sync(bl, &WL[(wn * 64 + nt * 16) * 72 + ks * 16], 72);
                    wmma::mma_sync(acc[mt][nt], ah, bh, acc[mt][nt]);
                    wmma::mma_sync(acc[mt][nt], al, bh, acc[mt][nt]);
                    wmma::mma_sync(acc[mt][nt], ah, bl, acc[mt][nt]);
                }
            }
        }
        __syncthreads();
    }
    #pragma unroll
    for (int mt = 0; mt < 2; mt++)
        #pragma unroll
        for (int nt = 0; nt < 4; nt++)
            wmma::store_matrix_sync(&FB[(wm * 32 + mt * 16) * 132 + wn * 64 + nt * 16],
                                    acc[mt][nt], 132, wmma::mem_row_major);
    __syncthreads();
    float s5 = bn5[0] * rsqrtf(bn5[3] + EPSF);
    float t5 = bn5[1] - bn5[2] * s5;
    for (int j = 0; j < 16; j++) {
        int g = t + j * 256;                 // 4096 groups of 4 cols
        int r = g >> 5, c4 = (g & 31) * 4;
        float4 v = *reinterpret_cast<float4*>(&FB[r * 132 + c4]);
        float* vp = &v.x;
        #pragma unroll
        for (int q = 0; q < 4; q++)
            vp[q] = fmaxf(fmaf(vp[q] + __ldg(&b5[nb + c4 + q]), s5, t5), 0.f);
        *reinterpret_cast<float4*>(&g_a5[(size_t)(b0 + r) * 512 + nb + c4]) = v;
    }
}

// ---------------- fc6/fc7 fp32 GEMM ----------------
__global__ __launch_bounds__(256) void k_gemm(
    int asel, const float* __restrict__ Wt, const float* __restrict__ bias,
    const float* __restrict__ bn, int N, int K, int relu)
{
    const float* A = asel ? g_a6 : g_a5;
    float* Out = asel ? g_a7 : g_a6;
    __shared__ float As[128 * 33];
    __shared__ float Ws[64 * 33];
    int rb = blockIdx.x * 128, nb = blockIdx.y * 64, t = threadIdx.x;
    int tx = t & 15, ty = t >> 4;
    float acc[8][4];
    #pragma unroll
    for (int ri = 0; ri < 8; ri++)
        #pragma unroll
        for (int ci = 0; ci < 4; ci++) acc[ri][ci] = 0.f;
    for (int k0 = 0; k0 < K; k0 += 32) {
        for (int i = t; i < 4096; i += 256)
            As[(i >> 5) * 33 + (i & 31)] = A[(size_t)(rb + (i >> 5)) * K + k0 + (i & 31)];
        for (int i = t; i < 2048; i += 256)
            Ws[(i >> 5) * 33 + (i & 31)] = Wt[(size_t)(nb + (i >> 5)) * K + k0 + (i & 31)];
        __syncthreads();
        #pragma unroll 4
        for (int c = 0; c < 32; c++) {
            float a[8], ww[4];
            #pragma unroll
            for (int ri = 0; ri < 8; ri++) a[ri] = As[(ty * 8 + ri) * 33 + c];
            #pragma unroll
            for (int ci = 0; ci < 4; ci++) ww[ci] = Ws[(tx * 4 + ci) * 33 + c];
            #pragma unroll
            for (int ri = 0; ri < 8; ri++)
                #pragma unroll
                for (int ci = 0; ci < 4; ci++) acc[ri][ci] = fmaf(a[ri], ww[ci], acc[ri][ci]);
        }
        __syncthreads();
    }
    float s = bn[0] * rsqrtf(bn[3] + EPSF);
    float tt = bn[1] - bn[2] * s;
    float bv[4];
    #pragma unroll
    for (int ci = 0; ci < 4; ci++) bv[ci] = bias[nb + tx * 4 + ci];
    #pragma unroll
    for (int ri = 0; ri < 8; ri++) {
        float z[4];
        #pragma unroll
        for (int ci = 0; ci < 4; ci++) {
            z[ci] = fmaf(acc[ri][ci] + bv[ci], s, tt);
            if (relu) z[ci] = fmaxf(z[ci], 0.f);
        }
        *reinterpret_cast<float4*>(&Out[(size_t)(rb + ty * 8 + ri) * N + nb + tx * 4]) =
            make_float4(z[0], z[1], z[2], z[3]);
    }
}

__global__ __launch_bounds__(256) void k_fc8(const float* __restrict__ w8,
                                             const float* __restrict__ b8,
                                             float* __restrict__ out)
{
    int t = threadIdx.x;
    int b = blockIdx.x * 32 + (t >> 3), n = t & 7;
    const float* ar = &g_a7[b * 128];
    const float* wr = &w8[n * 128];
    float acc = 0.f;
    #pragma unroll 8
    for (int k = 0; k < 128; k++) acc = fmaf(ar[k], wr[k], acc);
    out[b * 8 + n] = acc + b8[n];
}

// ---------------- launch ----------------
extern "C" void kernel_launch(void* const* d_in, const int* in_sizes, int n_in,
                              void* d_out, int out_size)
{
    const float* x   = (const float*)d_in[0];
    const float* bn0 = (const float*)d_in[1];
    const float* w1  = (const float*)d_in[2];
    const float* b1  = (const float*)d_in[3];
    const float* bn1 = (const float*)d_in[4];
    const float* w2  = (const float*)d_in[5];
    const float* b2  = (const float*)d_in[6];
    const float* bn2 = (const float*)d_in[7];
    const float* w3  = (const float*)d_in[8];
    const float* bn3 = (const float*)d_in[9];
    const float* w4  = (const float*)d_in[10];
    const float* bn4 = (const float*)d_in[11];
    const float* w5  = (const float*)d_in[12];
    const float* b5  = (const float*)d_in[13];
    const float* bn5 = (const float*)d_in[14];
    const float* w6  = (const float*)d_in[15];
    const float* b6  = (const float*)d_in[16];
    const float* bn6 = (const float*)d_in[17];
    const float* w7  = (const float*)d_in[18];
    const float* b7  = (const float*)d_in[19];
    const float* bn7 = (const float*)d_in[20];
    const float* w8  = (const float*)d_in[21];
    const float* b8  = (const float*)d_in[22];
    float* out = (float*)d_out;

    cudaFuncSetAttribute(k_lc_tc,  cudaFuncAttributeMaxDynamicSharedMemorySize, LC_SMEM);
    cudaFuncSetAttribute(k_fc5_tc, cudaFuncAttributeMaxDynamicSharedMemorySize, F5_SMEM);

    k_prep_w2 <<<144,   256>>>(w2);
    k_prep_w34<<<4096,  256>>>(w3, w4);
    k_prep_w5 <<<16384, 256>>>(w5);

    k_front<<<8192, 256>>>(x, bn0, w1, b1, bn1, b2, bn2);
    k_lc_tc<<<dim3(64, 128), 256, LC_SMEM>>>(bn3, bn4);
    k_fc5_tc<<<dim3(64, 4), 256, F5_SMEM>>>(b5, bn5);
    k_gemm<<<dim3(64, 8), 256>>>(0, w6, b6, bn6, 512, 512, 1);
    k_gemm<<<dim3(64, 2), 256>>>(1, w7, b7, bn7, 128, 512, 1);
    k_fc8<<<256, 256>>>(w8, b8, out);
}

// round 7
// speedup vs baseline: 2.1814x; 1.3679x over previous
#include <cuda_runtime.h>
#include <cuda_fp16.h>
#include <mma.h>
#include <cstdint>
using namespace nvcuda;
#define EPSF 1e-5f
// B=8192, C=64, H=8, W=16, P=128, F5=8192

// ---------------- scratch ----------------
__device__ __half g_w2th[36864], g_w2tl[36864];         // conv2 w [tap][o][c] hi/lo
__device__ __half g_w3h[524288], g_w3l[524288];         // lc3 w [p][o][c] hi/lo
__device__ __half g_w4h[524288], g_w4l[524288];         // lc4 w [p][o][c] hi/lo
__device__ __half g_w5h[4194304], g_w5l[4194304];       // fc5 w [n][p*64+c] hi/lo
__device__ __half g_a1h[67108864], g_a1l[67108864];     // conv1 out [p][b][c] hi/lo
__device__ __half g_a2h[67108864], g_a2l[67108864];     // conv2 out [p][b][c] hi/lo
__device__ __half g_a4h[67108864], g_a4l[67108864];     // lc4 out [b][p*64+c] hi/lo
__device__ float  g_a5[4194304], g_a6[4194304], g_a7[1048576];

__device__ __forceinline__ uint32_t packh2(__half a, __half b) {
    __half2 h = __halves2half2(a, b);
    return *reinterpret_cast<uint32_t*>(&h);
}
// load [rows x 64 halves] tile into smem rows of 72 halves (pad)
__device__ __forceinline__ void ldt(const __half* __restrict__ src, size_t rowStride,
                                    __half* dst, int t, int nt, int rows) {
    for (int i = t; i < rows * 8; i += nt) {
        int r = i >> 3, c = i & 7;
        *reinterpret_cast<uint4*>(&dst[r * 72 + c * 8]) =
            *reinterpret_cast<const uint4*>(&src[(size_t)r * rowStride + c * 8]);
    }
}

typedef wmma::fragment<wmma::matrix_a, 16,16,16, __half, wmma::row_major> FragA;
typedef wmma::fragment<wmma::matrix_b, 16,16,16, __half, wmma::col_major> FragB;
typedef wmma::fragment<wmma::accumulator, 16,16,16, float> FragC;

// ---------------- weight prep ----------------
__global__ void k_prep_w2(const float* __restrict__ w2) {
    int idx = blockIdx.x * 256 + threadIdx.x;
    if (idx >= 36864) return;
    int o = idx / 576, r = idx % 576;                    // in: [o][c][tap]
    int c = r / 9, tap = r % 9;
    float v = w2[idx];
    __half h = __float2half_rn(v);
    int d = tap * 4096 + o * 64 + c;                     // out: [tap][o][c]
    g_w2th[d] = h; g_w2tl[d] = __float2half_rn(v - __half2float(h));
}
__global__ void k_prep_w34(const float* __restrict__ w3, const float* __restrict__ w4) {
    int idx = blockIdx.x * 256 + threadIdx.x;            // 1048576
    int sel = idx >> 19, i = idx & 524287;
    int o = i >> 13, c = (i >> 7) & 63, p = i & 127;
    float v = sel ? w4[i] : w3[i];
    __half h = __float2half_rn(v), l = __float2half_rn(v - __half2float(h));
    int d = p * 4096 + o * 64 + c;
    if (sel) { g_w4h[d] = h; g_w4l[d] = l; } else { g_w3h[d] = h; g_w3l[d] = l; }
}
__global__ void k_prep_w5(const float* __restrict__ w5) {
    int idx = blockIdx.x * 256 + threadIdx.x;            // 4194304
    int n = idx >> 13, k = idx & 8191;
    int c = k >> 7, p = k & 127;
    float v = w5[idx];
    __half h = __float2half_rn(v);
    int d = n * 8192 + p * 64 + c;
    g_w5h[d] = h; g_w5l[d] = __float2half_rn(v - __half2float(h));
}

// ---------------- conv1: bn0 + conv1 + bn1 + relu -> g_a1 hi/lo [p][b][c] ----------------
__global__ __launch_bounds__(256) void k_conv1(
    const float* __restrict__ x, const float* __restrict__ bn0,
    const float* __restrict__ w1, const float* __restrict__ b1,
    const float* __restrict__ bn1)
{
    __shared__ float h0s[180];          // padded 10x18
    __shared__ float w1s[576];
    __shared__ float s1s[64], t1s[64], b1s[64];
    int b = blockIdx.x, t = threadIdx.x;
    if (t < 180) h0s[t] = 0.f;
    for (int i = t; i < 576; i += 256) w1s[i] = w1[i];
    if (t < 64) {
        float s = bn1[t] * rsqrtf(bn1[192 + t] + EPSF);
        s1s[t] = s; t1s[t] = bn1[64 + t] - bn1[128 + t] * s;
        b1s[t] = b1[t];
    }
    __syncthreads();
    if (t < 128) {
        float s0 = bn0[0] * rsqrtf(bn0[3] + EPSF);
        float t0 = bn0[1] - bn0[2] * s0;
        int i = t >> 4, j = t & 15;
        h0s[(i + 1) * 18 + (j + 1)] = x[b * 128 + j * 8 + i] * s0 + t0;
    }
    __syncthreads();
    for (int idx = t; idx < 8192; idx += 256) {
        int p = idx >> 6, o = idx & 63;
        int i = p >> 4, j = p & 15;
        float acc = 0.f;
        #pragma unroll
        for (int di = 0; di < 3; di++)
            #pragma unroll
            for (int dj = 0; dj < 3; dj++)
                acc = fmaf(h0s[(i + di) * 18 + (j + dj)], w1s[o * 9 + di * 3 + dj], acc);
        float z = fmaxf(fmaf(acc + b1s[o], s1s[o], t1s[o]), 0.f);
        __half h = __float2half_rn(z);
        size_t d = (size_t)p * 524288 + (size_t)b * 64 + o;
        g_a1h[d] = h;
        g_a1l[d] = __float2half_rn(z - __half2float(h));
    }
}

// ---------------- conv2 via wmma fp16x3 shift-GEMM + bn2 + relu ----------------
// grid (128 pixels fast, 64 btiles), 256 threads (8 warps, warp tile 32x32).
// smem: AH 0 (18432), AL 18432, WH 36864 (9216), WL 46080 -> 55296; FB f32 [128][68] aliases 0
#define C2_SMEM 55296
__global__ __launch_bounds__(256) void k_conv2(const float* __restrict__ b2,
                                               const float* __restrict__ bn2)
{
    extern __shared__ __align__(16) char smem[];
    __half* AH = reinterpret_cast<__half*>(smem);
    __half* AL = reinterpret_cast<__half*>(smem + 18432);
    __half* WH = reinterpret_cast<__half*>(smem + 36864);
    __half* WL = reinterpret_cast<__half*>(smem + 46080);
    float*  FB = reinterpret_cast<float*>(smem);            // [128][68]

    int p = blockIdx.x, b0 = blockIdx.y * 128, t = threadIdx.x;
    int w = t >> 5, wm = w & 3, wn = w >> 2;
    int i = p >> 4, j = p & 15;

    FragC acc[2][2];
    FragA ah, al;
    FragB bh, bl;
    #pragma unroll
    for (int mt = 0; mt < 2; mt++)
        #pragma unroll
        for (int nt = 0; nt < 2; nt++) wmma::fill_fragment(acc[mt][nt], 0.f);

    #pragma unroll
    for (int tap = 0; tap < 9; tap++) {
        int ii = i + tap / 3 - 1, jj = j + tap % 3 - 1;
        if (ii < 0 || ii >= 8 || jj < 0 || jj >= 16) continue;   // uniform per CTA
        int pp = ii * 16 + jj;
        __syncthreads();                                          // prior reads done
        size_t ab = (size_t)pp * 524288 + (size_t)b0 * 64;
        ldt(g_a1h + ab, 64, AH, t, 256, 128);
        ldt(g_a1l + ab, 64, AL, t, 256, 128);
        ldt(g_w2th + tap * 4096, 64, WH, t, 256, 64);
        ldt(g_w2tl + tap * 4096, 64, WL, t, 256, 64);
        __syncthreads();
        #pragma unroll
        for (int ks = 0; ks < 4; ks++) {
            #pragma unroll
            for (int mt = 0; mt < 2; mt++) {
                wmma::load_matrix_sync(ah, &AH[(wm * 32 + mt * 16) * 72 + ks * 16], 72);
                wmma::load_matrix_sync(al, &AL[(wm * 32 + mt * 16) * 72 + ks * 16], 72);
                #pragma unroll
                for (int nt = 0; nt < 2; nt++) {
                    wmma::load_matrix_sync(bh, &WH[(wn * 32 + nt * 16) * 72 + ks * 16], 72);
                    wmma::load_matrix_sync(bl, &WL[(wn * 32 + nt * 16) * 72 + ks * 16], 72);
                    wmma::mma_sync(acc[mt][nt], ah, bh, acc[mt][nt]);
                    wmma::mma_sync(acc[mt][nt], al, bh, acc[mt][nt]);
                    wmma::mma_sync(acc[mt][nt], ah, bl, acc[mt][nt]);
                }
            }
        }
    }
    __syncthreads();
    #pragma unroll
    for (int mt = 0; mt < 2; mt++)
        #pragma unroll
        for (int nt = 0; nt < 2; nt++)
            wmma::store_matrix_sync(&FB[(wm * 32 + mt * 16) * 68 + wn * 32 + nt * 16],
                                    acc[mt][nt], 68, wmma::mem_row_major);
    __syncthreads();
    for (int q = 0; q < 8; q++) {
        int g = t + q * 256;
        int r = g >> 4, c4 = (g & 15) * 4;
        float4 v = *reinterpret_cast<float4*>(&FB[r * 68 + c4]);
        float z[4]; __half hh[4];
        float* vp = &v.x;
        #pragma unroll
        for (int qq = 0; qq < 4; qq++) {
            int o = c4 + qq;
            float s2 = __ldg(&bn2[o]) * rsqrtf(__ldg(&bn2[192 + o]) + EPSF);
            float t2 = __ldg(&bn2[64 + o]) - __ldg(&bn2[128 + o]) * s2;
            z[qq] = fmaxf(fmaf(vp[qq] + __ldg(&b2[o]), s2, t2), 0.f);
            hh[qq] = __float2half_rn(z[qq]);
        }
        size_t o2 = (size_t)p * 524288 + (size_t)(b0 + r) * 64 + c4;
        *reinterpret_cast<uint2*>(&g_a2h[o2]) =
            make_uint2(packh2(hh[0], hh[1]), packh2(hh[2], hh[3]));
        *reinterpret_cast<uint2*>(&g_a2l[o2]) = make_uint2(
            packh2(__float2half_rn(z[0] - __half2float(hh[0])), __float2half_rn(z[1] - __half2float(hh[1]))),
            packh2(__float2half_rn(z[2] - __half2float(hh[2])), __float2half_rn(z[3] - __half2float(hh[3]))));
    }
}

// ---------------- lc3+lc4 via wmma fp16x3, chained in smem ----------------
#define LC_SMEM 111616
__global__ __launch_bounds__(256) void k_lc_tc(const float* __restrict__ bn3,
                                               const float* __restrict__ bn4)
{
    extern __shared__ __align__(16) char smem[];
    __half* AH  = reinterpret_cast<__half*>(smem);
    __half* AL  = reinterpret_cast<__half*>(smem + 18432);
    __half* W3H = reinterpret_cast<__half*>(smem + 36864);
    __half* W3L = reinterpret_cast<__half*>(smem + 46080);
    __half* W4H = reinterpret_cast<__half*>(smem + 55296);
    __half* W4L = reinterpret_cast<__half*>(smem + 64512);
    __half* XH  = reinterpret_cast<__half*>(smem + 73728);
    __half* XL  = reinterpret_cast<__half*>(smem + 92160);
    float*  BN  = reinterpret_cast<float*>(smem + 110592);   // s3|t3|s4|t4
    float*  FB  = reinterpret_cast<float*>(smem);            // [128][68]

    int p = blockIdx.y, b0 = blockIdx.x * 128, t = threadIdx.x;
    int w = t >> 5, wm = w & 3, wn = w >> 2;

    if (t < 64) {
        float s = bn3[t] * rsqrtf(bn3[192 + t] + EPSF);
        BN[t] = s; BN[64 + t] = bn3[64 + t] - bn3[128 + t] * s;
        s = bn4[t] * rsqrtf(bn4[192 + t] + EPSF);
        BN[128 + t] = s; BN[192 + t] = bn4[64 + t] - bn4[128 + t] * s;
    }
    size_t ab = (size_t)p * 524288 + (size_t)b0 * 64;
    ldt(g_a2h + ab, 64, AH, t, 256, 128);
    ldt(g_a2l + ab, 64, AL, t, 256, 128);
    ldt(g_w3h + p * 4096, 64, W3H, t, 256, 64);
    ldt(g_w3l + p * 4096, 64, W3L, t, 256, 64);
    ldt(g_w4h + p * 4096, 64, W4H, t, 256, 64);
    ldt(g_w4l + p * 4096, 64, W4L, t, 256, 64);
    __syncthreads();

    FragC acc[2][2];
    FragA ah, al;
    FragB bh, bl;
    #pragma unroll
    for (int mt = 0; mt < 2; mt++)
        #pragma unroll
        for (int nt = 0; nt < 2; nt++) wmma::fill_fragment(acc[mt][nt], 0.f);
    #pragma unroll
    for (int ks = 0; ks < 4; ks++) {
        #pragma unroll
        for (int mt = 0; mt < 2; mt++) {
            wmma::load_matrix_sync(ah, &AH[(wm * 32 + mt * 16) * 72 + ks * 16], 72);
            wmma::load_matrix_sync(al, &AL[(wm * 32 + mt * 16) * 72 + ks * 16], 72);
            #pragma unroll
            for (int nt = 0; nt < 2; nt++) {
                wmma::load_matrix_sync(bh, &W3H[(wn * 32 + nt * 16) * 72 + ks * 16], 72);
                wmma::load_matrix_sync(bl, &W3L[(wn * 32 + nt * 16) * 72 + ks * 16], 72);
                wmma::mma_sync(acc[mt][nt], ah, bh, acc[mt][nt]);
                wmma::mma_sync(acc[mt][nt], al, bh, acc[mt][nt]);
                wmma::mma_sync(acc[mt][nt], ah, bl, acc[mt][nt]);
            }
        }
    }
    __syncthreads();
    #pragma unroll
    for (int mt = 0; mt < 2; mt++)
        #pragma unroll
        for (int nt = 0; nt < 2; nt++)
            wmma::store_matrix_sync(&FB[(wm * 32 + mt * 16) * 68 + wn * 32 + nt * 16],
                                    acc[mt][nt], 68, wmma::mem_row_major);
    __syncthreads();
    for (int q = 0; q < 8; q++) {
        int g = t + q * 256;
        int r = g >> 4, c4 = (g & 15) * 4;
        float4 v = *reinterpret_cast<float4*>(&FB[r * 68 + c4]);
        float z[4]; __half hh[4];
        float* vp = &v.x;
        #pragma unroll
        for (int qq = 0; qq < 4; qq++) {
            z[qq] = fmaxf(fmaf(vp[qq], BN[c4 + qq], BN[64 + c4 + qq]), 0.f);
            hh[qq] = __float2half_rn(z[qq]);
        }
        *reinterpret_cast<uint32_t*>(&XH[r * 72 + c4])     = packh2(hh[0], hh[1]);
        *reinterpret_cast<uint32_t*>(&XH[r * 72 + c4 + 2]) = packh2(hh[2], hh[3]);
        *reinterpret_cast<uint32_t*>(&XL[r * 72 + c4]) =
            packh2(__float2half_rn(z[0] - __half2float(hh[0])), __float2half_rn(z[1] - __half2float(hh[1])));
        *reinterpret_cast<uint32_t*>(&XL[r * 72 + c4 + 2]) =
            packh2(__float2half_rn(z[2] - __half2float(hh[2])), __float2half_rn(z[3] - __half2float(hh[3])));
    }
    __syncthreads();
    #pragma unroll
    for (int mt = 0; mt < 2; mt++)
        #pragma unroll
        for (int nt = 0; nt < 2; nt++) wmma::fill_fragment(acc[mt][nt], 0.f);
    #pragma unroll
    for (int ks = 0; ks < 4; ks++) {
        #pragma unroll
        for (int mt = 0; mt < 2; mt++) {
            wmma::load_matrix_sync(ah, &XH[(wm * 32 + mt * 16) * 72 + ks * 16], 72);
            wmma::load_matrix_sync(al, &XL[(wm * 32 + mt * 16) * 72 + ks * 16], 72);
            #pragma unroll
            for (int nt = 0; nt < 2; nt++) {
                wmma::load_matrix_sync(bh, &W4H[(wn * 32 + nt * 16) * 72 + ks * 16], 72);
                wmma::load_matrix_sync(bl, &W4L[(wn * 32 + nt * 16) * 72 + ks * 16], 72);
                wmma::mma_sync(acc[mt][nt], ah, bh, acc[mt][nt]);
                wmma::mma_sync(acc[mt][nt], al, bh, acc[mt][nt]);
                wmma::mma_sync(acc[mt][nt], ah, bl, acc[mt][nt]);
            }
        }
    }
    __syncthreads();
    #pragma unroll
    for (int mt = 0; mt < 2; mt++)
        #pragma unroll
        for (int nt = 0; nt < 2; nt++)
            wmma::store_matrix_sync(&FB[(wm * 32 + mt * 16) * 68 + wn * 32 + nt * 16],
                                    acc[mt][nt], 68, wmma::mem_row_major);
    __syncthreads();
    for (int q = 0; q < 8; q++) {
        int g = t + q * 256;
        int r = g >> 4, c4 = (g & 15) * 4;
        float4 v = *reinterpret_cast<float4*>(&FB[r * 68 + c4]);
        float z[4]; __half hh[4];
        float* vp = &v.x;
        #pragma unroll
        for (int qq = 0; qq < 4; qq++) {
            z[qq] = fmaxf(fmaf(vp[qq], BN[128 + c4 + qq], BN[192 + c4 + qq]), 0.f);
            hh[qq] = __float2half_rn(z[qq]);
        }
        size_t o2 = (size_t)(b0 + r) * 8192 + p * 64 + c4;
        *reinterpret_cast<uint2*>(&g_a4h[o2]) =
            make_uint2(packh2(hh[0], hh[1]), packh2(hh[2], hh[3]));
        *reinterpret_cast<uint2*>(&g_a4l[o2]) = make_uint2(
            packh2(__float2half_rn(z[0] - __half2float(hh[0])), __float2half_rn(z[1] - __half2float(hh[1]))),
            packh2(__float2half_rn(z[2] - __half2float(hh[2])), __float2half_rn(z[3] - __half2float(hh[3]))));
    }
}

// ---------------- fc5 via wmma fp16x3 ----------------
#define F5_SMEM 73728
__global__ __launch_bounds__(256) void k_fc5_tc(const float* __restrict__ b5,
                                                const float* __restrict__ bn5)
{
    extern __shared__ __align__(16) char smem[];
    __half* AH = reinterpret_cast<__half*>(smem);
    __half* AL = reinterpret_cast<__half*>(smem + 18432);
    __half* WH = reinterpret_cast<__half*>(smem + 36864);
    __half* WL = reinterpret_cast<__half*>(smem + 55296);
    float*  FB = reinterpret_cast<float*>(smem);            // [128][132]

    int b0 = blockIdx.x * 128, nb = blockIdx.y * 128, t = threadIdx.x;
    int w = t >> 5, wm = w & 3, wn = w >> 2;

    FragC acc[2][4];
    FragA ah, al;
    FragB bh, bl;
    #pragma unroll
    for (int mt = 0; mt < 2; mt++)
        #pragma unroll
        for (int nt = 0; nt < 4; nt++) wmma::fill_fragment(acc[mt][nt], 0.f);

    for (int k = 0; k < 128; k++) {
        ldt(g_a4h + (size_t)b0 * 8192 + k * 64, 8192, AH, t, 256, 128);
        ldt(g_a4l + (size_t)b0 * 8192 + k * 64, 8192, AL, t, 256, 128);
        ldt(g_w5h + (size_t)nb * 8192 + k * 64, 8192, WH, t, 256, 128);
        ldt(g_w5l + (size_t)nb * 8192 + k * 64, 8192, WL, t, 256, 128);
        __syncthreads();
        #pragma unroll
        for (int ks = 0; ks < 4; ks++) {
            #pragma unroll
            for (int mt = 0; mt < 2; mt++) {
                wmma::load_matrix_sync(ah, &AH[(wm * 32 + mt * 16) * 72 + ks * 16], 72);
                wmma::load_matrix_sync(al, &AL[(wm * 32 + mt * 16) * 72 + ks * 16], 72);
                #pragma unroll
                for (int nt = 0; nt < 4; nt++) {
                    wmma::load_matrix_sync(bh, &WH[(wn * 64 + nt * 16) * 72 + ks * 16], 72);
                    wmma::load_matrix_sync(bl, &WL[(wn * 64 + nt * 16) * 72 + ks * 16], 72);
                    wmma::mma_sync(acc[mt][nt], ah, bh, acc[mt][nt]);
                    wmma::mma_sync(acc[mt][nt], al, bh, acc[mt][nt]);
                    wmma::mma_sync(acc[mt][nt], ah, bl, acc[mt][nt]);
                }
            }
        }
        __syncthreads();
    }
    #pragma unroll
    for (int mt = 0; mt < 2; mt++)
        #pragma unroll
        for (int nt = 0; nt < 4; nt++)
            wmma::store_matrix_sync(&FB[(wm * 32 + mt * 16) * 132 + wn * 64 + nt * 16],
                                    acc[mt][nt], 132, wmma::mem_row_major);
    __syncthreads();
    float s5 = bn5[0] * rsqrtf(bn5[3] + EPSF);
    float t5 = bn5[1] - bn5[2] * s5;
    for (int q = 0; q < 16; q++) {
        int g = t + q * 256;
        int r = g >> 5, c4 = (g & 31) * 4;
        float4 v = *reinterpret_cast<float4*>(&FB[r * 132 + c4]);
        float* vp = &v.x;
        #pragma unroll
        for (int qq = 0; qq < 4; qq++)
            vp[qq] = fmaxf(fmaf(vp[qq] + __ldg(&b5[nb + c4 + qq]), s5, t5), 0.f);
        *reinterpret_cast<float4*>(&g_a5[(size_t)(b0 + r) * 512 + nb + c4]) = v;
    }
}

// ---------------- fc6/fc7 fp32 GEMM ----------------
__global__ __launch_bounds__(256) void k_gemm(
    int asel, const float* __restrict__ Wt, const float* __restrict__ bias,
    const float* __restrict__ bn, int N, int K, int relu)
{
    const float* A = asel ? g_a6 : g_a5;
    float* Out = asel ? g_a7 : g_a6;
    __shared__ float As[128 * 33];
    __shared__ float Ws[64 * 33];
    int rb = blockIdx.x * 128, nb = blockIdx.y * 64, t = threadIdx.x;
    int tx = t & 15, ty = t >> 4;
    float acc[8][4];
    #pragma unroll
    for (int ri = 0; ri < 8; ri++)
        #pragma unroll
        for (int ci = 0; ci < 4; ci++) acc[ri][ci] = 0.f;
    for (int k0 = 0; k0 < K; k0 += 32) {
        for (int i = t; i < 4096; i += 256)
            As[(i >> 5) * 33 + (i & 31)] = A[(size_t)(rb + (i >> 5)) * K + k0 + (i & 31)];
        for (int i = t; i < 2048; i += 256)
            Ws[(i >> 5) * 33 + (i & 31)] = Wt[(size_t)(nb + (i >> 5)) * K + k0 + (i & 31)];
        __syncthreads();
        #pragma unroll 4
        for (int c = 0; c < 32; c++) {
            float a[8], ww[4];
            #pragma unroll
            for (int ri = 0; ri < 8; ri++) a[ri] = As[(ty * 8 + ri) * 33 + c];
            #pragma unroll
            for (int ci = 0; ci < 4; ci++) ww[ci] = Ws[(tx * 4 + ci) * 33 + c];
            #pragma unroll
            for (int ri = 0; ri < 8; ri++)
                #pragma unroll
                for (int ci = 0; ci < 4; ci++) acc[ri][ci] = fmaf(a[ri], ww[ci], acc[ri][ci]);
        }
        __syncthreads();
    }
    float s = bn[0] * rsqrtf(bn[3] + EPSF);
    float tt = bn[1] - bn[2] * s;
    float bv[4];
    #pragma unroll
    for (int ci = 0; ci < 4; ci++) bv[ci] = bias[nb + tx * 4 + ci];
    #pragma unroll
    for (int ri = 0; ri < 8; ri++) {
        float z[4];
        #pragma unroll
        for (int ci = 0; ci < 4; ci++) {
            z[ci] = fmaf(acc[ri][ci] + bv[ci], s, tt);
            if (relu) z[ci] = fmaxf(z[ci], 0.f);
        }
        *reinterpret_cast<float4*>(&Out[(size_t)(rb + ty * 8 + ri) * N + nb + tx * 4]) =
            make_float4(z[0], z[1], z[2], z[3]);
    }
}

__global__ __launch_bounds__(256) void k_fc8(const float* __restrict__ w8,
                                             const float* __restrict__ b8,
                                             float* __restrict__ out)
{
    int t = threadIdx.x;
    int b = blockIdx.x * 32 + (t >> 3), n = t & 7;
    const float* ar = &g_a7[b * 128];
    const float* wr = &w8[n * 128];
    float acc = 0.f;
    #pragma unroll 8
    for (int k = 0; k < 128; k++) acc = fmaf(ar[k], wr[k], acc);
    out[b * 8 + n] = acc + b8[n];
}

// ---------------- launch ----------------
extern "C" void kernel_launch(void* const* d_in, const int* in_sizes, int n_in,
                              void* d_out, int out_size)
{
    const float* x   = (const float*)d_in[0];
    const float* bn0 = (const float*)d_in[1];
    const float* w1  = (const float*)d_in[2];
    const float* b1  = (const float*)d_in[3];
    const float* bn1 = (const float*)d_in[4];
    const float* w2  = (const float*)d_in[5];
    const float* b2  = (const float*)d_in[6];
    const float* bn2 = (const float*)d_in[7];
    const float* w3  = (const float*)d_in[8];
    const float* bn3 = (const float*)d_in[9];
    const float* w4  = (const float*)d_in[10];
    const float* bn4 = (const float*)d_in[11];
    const float* w5  = (const float*)d_in[12];
    const float* b5  = (const float*)d_in[13];
    const float* bn5 = (const float*)d_in[14];
    const float* w6  = (const float*)d_in[15];
    const float* b6  = (const float*)d_in[16];
    const float* bn6 = (const float*)d_in[17];
    const float* w7  = (const float*)d_in[18];
    const float* b7  = (const float*)d_in[19];
    const float* bn7 = (const float*)d_in[20];
    const float* w8  = (const float*)d_in[21];
    const float* b8  = (const float*)d_in[22];
    float* out = (float*)d_out;

    cudaFuncSetAttribute(k_conv2,  cudaFuncAttributeMaxDynamicSharedMemorySize, C2_SMEM);
    cudaFuncSetAttribute(k_lc_tc,  cudaFuncAttributeMaxDynamicSharedMemorySize, LC_SMEM);
    cudaFuncSetAttribute(k_fc5_tc, cudaFuncAttributeMaxDynamicSharedMemorySize, F5_SMEM);

    k_prep_w2 <<<144,   256>>>(w2);
    k_prep_w34<<<4096,  256>>>(w3, w4);
    k_prep_w5 <<<16384, 256>>>(w5);

    k_conv1<<<8192, 256>>>(x, bn0, w1, b1, bn1);
    k_conv2<<<dim3(128, 64), 256, C2_SMEM>>>(b2, bn2);
    k_lc_tc<<<dim3(64, 128), 256, LC_SMEM>>>(bn3, bn4);
    k_fc5_tc<<<dim3(64, 4), 256, F5_SMEM>>>(b5, bn5);
    k_gemm<<<dim3(64, 8), 256>>>(0, w6, b6, bn6, 512, 512, 1);
    k_gemm<<<dim3(64, 2), 256>>>(1, w7, b7, bn7, 128, 512, 1);
    k_fc8<<<256, 256>>>(w8, b8, out);
}

// round 10
// speedup vs baseline: 3.1217x; 1.4311x over previous
#include <cuda_runtime.h>
#include <cuda_fp16.h>
#include <cuda_pipeline.h>
#include <mma.h>
#include <cstdint>
using namespace nvcuda;
#define EPSF 1e-5f
// B=8192, C=64, H=8, W=16, P=128, F5=8192

// ---------------- scratch ----------------
__device__ __half g_w2th[36864], g_w2tl[36864];         // conv2 w [tap][o][c] hi/lo
__device__ __half g_w3h[524288], g_w3l[524288];         // lc3 w [p][o][c] hi/lo
__device__ __half g_w4h[524288], g_w4l[524288];         // lc4 w [p][o][c] hi/lo
__device__ __half g_w5h[4194304], g_w5l[4194304];       // fc5 w [n][p*64+c] hi/lo
__device__ __half g_a1h[67108864], g_a1l[67108864];     // conv1 out [p][b][c] hi/lo
__device__ __half g_a2h[67108864], g_a2l[67108864];     // conv2 out [p][b][c] hi/lo
__device__ __half g_a4h[67108864], g_a4l[67108864];     // lc4 out [b][p*64+c] hi/lo
__device__ float  g_a5[4194304], g_a6[4194304], g_a7[1048576];

__device__ __forceinline__ uint32_t packh2(__half a, __half b) {
    __half2 h = __halves2half2(a, b);
    return *reinterpret_cast<uint32_t*>(&h);
}
// sync load [rows x 64 halves] tile into smem rows of 72 halves (pad)
__device__ __forceinline__ void ldt(const __half* __restrict__ src, size_t rowStride,
                                    __half* dst, int t, int nt, int rows) {
    for (int i = t; i < rows * 8; i += nt) {
        int r = i >> 3, c = i & 7;
        *reinterpret_cast<uint4*>(&dst[r * 72 + c * 8]) =
            *reinterpret_cast<const uint4*>(&src[(size_t)r * rowStride + c * 8]);
    }
}
// async version (cp.async 16B)
__device__ __forceinline__ void ldta(const __half* __restrict__ src, size_t rowStride,
                                     __half* dst, int t, int nt, int rows) {
    for (int i = t; i < rows * 8; i += nt) {
        int r = i >> 3, c = i & 7;
        __pipeline_memcpy_async(&dst[r * 72 + c * 8], &src[(size_t)r * rowStride + c * 8], 16);
    }
}

typedef wmma::fragment<wmma::matrix_a, 16,16,16, __half, wmma::row_major> FragA;
typedef wmma::fragment<wmma::matrix_b, 16,16,16, __half, wmma::col_major> FragB;
typedef wmma::fragment<wmma::accumulator, 16,16,16, float> FragC;

// ---------------- weight prep ----------------
__global__ void k_prep_w2(const float* __restrict__ w2) {
    int idx = blockIdx.x * 256 + threadIdx.x;
    if (idx >= 36864) return;
    int o = idx / 576, r = idx % 576;                    // in: [o][c][tap]
    int c = r / 9, tap = r % 9;
    float v = w2[idx];
    __half h = __float2half_rn(v);
    int d = tap * 4096 + o * 64 + c;                     // out: [tap][o][c]
    g_w2th[d] = h; g_w2tl[d] = __float2half_rn(v - __half2float(h));
}
__global__ void k_prep_w34(const float* __restrict__ w3, const float* __restrict__ w4) {
    int idx = blockIdx.x * 256 + threadIdx.x;            // 1048576
    int sel = idx >> 19, i = idx & 524287;
    int o = i >> 13, c = (i >> 7) & 63, p = i & 127;
    float v = sel ? w4[i] : w3[i];
    __half h = __float2half_rn(v), l = __float2half_rn(v - __half2float(h));
    int d = p * 4096 + o * 64 + c;
    if (sel) { g_w4h[d] = h; g_w4l[d] = l; } else { g_w3h[d] = h; g_w3l[d] = l; }
}
__global__ void k_prep_w5(const float* __restrict__ w5) {
    int idx = blockIdx.x * 256 + threadIdx.x;            // 4194304
    int n = idx >> 13, k = idx & 8191;
    int c = k >> 7, p = k & 127;
    float v = w5[idx];
    __half h = __float2half_rn(v);
    int d = n * 8192 + p * 64 + c;
    g_w5h[d] = h; g_w5l[d] = __float2half_rn(v - __half2float(h));
}

// ---------------- conv1: bn0 + conv1 + bn1 + relu -> g_a1 hi/lo [p][b][c] ----------------
__global__ __launch_bounds__(256) void k_conv1(
    const float* __restrict__ x, const float* __restrict__ bn0,
    const float* __restrict__ w1, const float* __restrict__ b1,
    const float* __restrict__ bn1)
{
    __shared__ float h0s[180];
    __shared__ float w1s[576];
    __shared__ float s1s[64], t1s[64], b1s[64];
    int b = blockIdx.x, t = threadIdx.x;
    if (t < 180) h0s[t] = 0.f;
    for (int i = t; i < 576; i += 256) w1s[i] = w1[i];
    if (t < 64) {
        float s = bn1[t] * rsqrtf(bn1[192 + t] + EPSF);
        s1s[t] = s; t1s[t] = bn1[64 + t] - bn1[128 + t] * s;
        b1s[t] = b1[t];
    }
    __syncthreads();
    if (t < 128) {
        float s0 = bn0[0] * rsqrtf(bn0[3] + EPSF);
        float t0 = bn0[1] - bn0[2] * s0;
        int i = t >> 4, j = t & 15;
        h0s[(i + 1) * 18 + (j + 1)] = x[b * 128 + j * 8 + i] * s0 + t0;
    }
    __syncthreads();
    for (int idx = t; idx < 8192; idx += 256) {
        int p = idx >> 6, o = idx & 63;
        int i = p >> 4, j = p & 15;
        float acc = 0.f;
        #pragma unroll
        for (int di = 0; di < 3; di++)
            #pragma unroll
            for (int dj = 0; dj < 3; dj++)
                acc = fmaf(h0s[(i + di) * 18 + (j + dj)], w1s[o * 9 + di * 3 + dj], acc);
        float z = fmaxf(fmaf(acc + b1s[o], s1s[o], t1s[o]), 0.f);
        __half h = __float2half_rn(z);
        size_t d = (size_t)p * 524288 + (size_t)b * 64 + o;
        g_a1h[d] = h;
        g_a1l[d] = __float2half_rn(z - __half2float(h));
    }
}

// ---------------- conv2 via wmma fp16x3 shift-GEMM, cp.async double-buffered taps ----------------
// grid (128 pixels fast, 64 btiles), 256 threads. Two 55296B buffers: AH 0, AL 18432, WH 36864, WL 46080.
#define C2_BUF 55296
#define C2_SMEM 110592
__global__ __launch_bounds__(256) void k_conv2(const float* __restrict__ b2,
                                               const float* __restrict__ bn2)
{
    extern __shared__ __align__(16) char smem[];
    float* FB = reinterpret_cast<float*>(smem);             // [128][68] epilogue alias

    int p = blockIdx.x, b0 = blockIdx.y * 128, t = threadIdx.x;
    int w = t >> 5, wm = w & 3, wn = w >> 2;
    int i = p >> 4, j = p & 15;

    int vt[9], nv = 0;
    #pragma unroll
    for (int tap = 0; tap < 9; tap++) {
        int ii = i + tap / 3 - 1, jj = j + tap % 3 - 1;
        if (ii >= 0 && ii < 8 && jj >= 0 && jj < 16) vt[nv++] = tap;
    }

    FragC acc[2][2];
    FragA ah, al;
    FragB bh, bl;
    #pragma unroll
    for (int mt = 0; mt < 2; mt++)
        #pragma unroll
        for (int nt = 0; nt < 2; nt++) wmma::fill_fragment(acc[mt][nt], 0.f);

    // issue tap q into buffer bf
    auto issue = [&](int q, int bf) {
        int tap = vt[q];
        int pp = (i + tap / 3 - 1) * 16 + (j + tap % 3 - 1);
        char* B = smem + bf * C2_BUF;
        size_t ab = (size_t)pp * 524288 + (size_t)b0 * 64;
        ldta(g_a1h + ab, 64, reinterpret_cast<__half*>(B), t, 256, 128);
        ldta(g_a1l + ab, 64, reinterpret_cast<__half*>(B + 18432), t, 256, 128);
        ldta(g_w2th + tap * 4096, 64, reinterpret_cast<__half*>(B + 36864), t, 256, 64);
        ldta(g_w2tl + tap * 4096, 64, reinterpret_cast<__half*>(B + 46080), t, 256, 64);
        __pipeline_commit();
    };

    issue(0, 0);
    for (int q = 0; q < nv; q++) {
        if (q + 1 < nv) issue(q + 1, (q + 1) & 1);
        __pipeline_wait_prior((q + 1 < nv) ? 1 : 0);
        __syncthreads();
        char* B = smem + (q & 1) * C2_BUF;
        __half* AH = reinterpret_cast<__half*>(B);
        __half* AL = reinterpret_cast<__half*>(B + 18432);
        __half* WH = reinterpret_cast<__half*>(B + 36864);
        __half* WL = reinterpret_cast<__half*>(B + 46080);
        #pragma unroll
        for (int ks = 0; ks < 4; ks++) {
            #pragma unroll
            for (int mt = 0; mt < 2; mt++) {
                wmma::load_matrix_sync(ah, &AH[(wm * 32 + mt * 16) * 72 + ks * 16], 72);
                wmma::load_matrix_sync(al, &AL[(wm * 32 + mt * 16) * 72 + ks * 16], 72);
                #pragma unroll
                for (int nt = 0; nt < 2; nt++) {
                    wmma::load_matrix_sync(bh, &WH[(wn * 32 + nt * 16) * 72 + ks * 16], 72);
                    wmma::load_matrix_sync(bl, &WL[(wn * 32 + nt * 16) * 72 + ks * 16], 72);
                    wmma::mma_sync(acc[mt][nt], ah, bh, acc[mt][nt]);
                    wmma::mma_sync(acc[mt][nt], al, bh, acc[mt][nt]);
                    wmma::mma_sync(acc[mt][nt], ah, bl, acc[mt][nt]);
                }
            }
        }
        __syncthreads();
    }
    #pragma unroll
    for (int mt = 0; mt < 2; mt++)
        #pragma unroll
        for (int nt = 0; nt < 2; nt++)
            wmma::store_matrix_sync(&FB[(wm * 32 + mt * 16) * 68 + wn * 32 + nt * 16],
                                    acc[mt][nt], 68, wmma::mem_row_major);
    __syncthreads();
    for (int q = 0; q < 8; q++) {
        int g = t + q * 256;
        int r = g >> 4, c4 = (g & 15) * 4;
        float4 v = *reinterpret_cast<float4*>(&FB[r * 68 + c4]);
        float z[4]; __half hh[4];
        float* vp = &v.x;
        #pragma unroll
        for (int qq = 0; qq < 4; qq++) {
            int o = c4 + qq;
            float s2 = __ldg(&bn2[o]) * rsqrtf(__ldg(&bn2[192 + o]) + EPSF);
            float t2 = __ldg(&bn2[64 + o]) - __ldg(&bn2[128 + o]) * s2;
            z[qq] = fmaxf(fmaf(vp[qq] + __ldg(&b2[o]), s2, t2), 0.f);
            hh[qq] = __float2half_rn(z[qq]);
        }
        size_t o2 = (size_t)p * 524288 + (size_t)(b0 + r) * 64 + c4;
        *reinterpret_cast<uint2*>(&g_a2h[o2]) =
            make_uint2(packh2(hh[0], hh[1]), packh2(hh[2], hh[3]));
        *reinterpret_cast<uint2*>(&g_a2l[o2]) = make_uint2(
            packh2(__float2half_rn(z[0] - __half2float(hh[0])), __float2half_rn(z[1] - __half2float(hh[1]))),
            packh2(__float2half_rn(z[2] - __half2float(hh[2])), __float2half_rn(z[3] - __half2float(hh[3]))));
    }
}

// ---------------- lc3+lc4 via wmma fp16x3, chained in smem ----------------
#define LC_SMEM 111616
__global__ __launch_bounds__(256) void k_lc_tc(const float* __restrict__ bn3,
                                               const float* __restrict__ bn4)
{
    extern __shared__ __align__(16) char smem[];
    __half* AH  = reinterpret_cast<__half*>(smem);
    __half* AL  = reinterpret_cast<__half*>(smem + 18432);
    __half* W3H = reinterpret_cast<__half*>(smem + 36864);
    __half* W3L = reinterpret_cast<__half*>(smem + 46080);
    __half* W4H = reinterpret_cast<__half*>(smem + 55296);
    __half* W4L = reinterpret_cast<__half*>(smem + 64512);
    __half* XH  = reinterpret_cast<__half*>(smem + 73728);
    __half* XL  = reinterpret_cast<__half*>(smem + 92160);
    float*  BN  = reinterpret_cast<float*>(smem + 110592);
    float*  FB  = reinterpret_cast<float*>(smem);            // [128][68]

    int p = blockIdx.y, b0 = blockIdx.x * 128, t = threadIdx.x;
    int w = t >> 5, wm = w & 3, wn = w >> 2;

    if (t < 64) {
        float s = bn3[t] * rsqrtf(bn3[192 + t] + EPSF);
        BN[t] = s; BN[64 + t] = bn3[64 + t] - bn3[128 + t] * s;
        s = bn4[t] * rsqrtf(bn4[192 + t] + EPSF);
        BN[128 + t] = s; BN[192 + t] = bn4[64 + t] - bn4[128 + t] * s;
    }
    size_t ab = (size_t)p * 524288 + (size_t)b0 * 64;
    ldta(g_a2h + ab, 64, AH, t, 256, 128);
    ldta(g_a2l + ab, 64, AL, t, 256, 128);
    ldta(g_w3h + p * 4096, 64, W3H, t, 256, 64);
    ldta(g_w3l + p * 4096, 64, W3L, t, 256, 64);
    ldta(g_w4h + p * 4096, 64, W4H, t, 256, 64);
    ldta(g_w4l + p * 4096, 64, W4L, t, 256, 64);
    __pipeline_commit();
    __pipeline_wait_prior(0);
    __syncthreads();

    FragC acc[2][2];
    FragA ah, al;
    FragB bh, bl;
    #pragma unroll
    for (int mt = 0; mt < 2; mt++)
        #pragma unroll
        for (int nt = 0; nt < 2; nt++) wmma::fill_fragment(acc[mt][nt], 0.f);
    #pragma unroll
    for (int ks = 0; ks < 4; ks++) {
        #pragma unroll
        for (int mt = 0; mt < 2; mt++) {
            wmma::load_matrix_sync(ah, &AH[(wm * 32 + mt * 16) * 72 + ks * 16], 72);
            wmma::load_matrix_sync(al, &AL[(wm * 32 + mt * 16) * 72 + ks * 16], 72);
            #pragma unroll
            for (int nt = 0; nt < 2; nt++) {
                wmma::load_matrix_sync(bh, &W3H[(wn * 32 + nt * 16) * 72 + ks * 16], 72);
                wmma::load_matrix_sync(bl, &W3L[(wn * 32 + nt * 16) * 72 + ks * 16], 72);
                wmma::mma_sync(acc[mt][nt], ah, bh, acc[mt][nt]);
                wmma::mma_sync(acc[mt][nt], al, bh, acc[mt][nt]);
                wmma::mma_sync(acc[mt][nt], ah, bl, acc[mt][nt]);
            }
        }
    }
    __syncthreads();
    #pragma unroll
    for (int mt = 0; mt < 2; mt++)
        #pragma unroll
        for (int nt = 0; nt < 2; nt++)
            wmma::store_matrix_sync(&FB[(wm * 32 + mt * 16) * 68 + wn * 32 + nt * 16],
                                    acc[mt][nt], 68, wmma::mem_row_major);
    __syncthreads();
    for (int q = 0; q < 8; q++) {
        int g = t + q * 256;
        int r = g >> 4, c4 = (g & 15) * 4;
        float4 v = *reinterpret_cast<float4*>(&FB[r * 68 + c4]);
        float z[4]; __half hh[4];
        float* vp = &v.x;
        #pragma unroll
        for (int qq = 0; qq < 4; qq++) {
            z[qq] = fmaxf(fmaf(vp[qq], BN[c4 + qq], BN[64 + c4 + qq]), 0.f);
            hh[qq] = __float2half_rn(z[qq]);
        }
        *reinterpret_cast<uint32_t*>(&XH[r * 72 + c4])     = packh2(hh[0], hh[1]);
        *reinterpret_cast<uint32_t*>(&XH[r * 72 + c4 + 2]) = packh2(hh[2], hh[3]);
        *reinterpret_cast<uint32_t*>(&XL[r * 72 + c4]) =
            packh2(__float2half_rn(z[0] - __half2float(hh[0])), __float2half_rn(z[1] - __half2float(hh[1])));
        *reinterpret_cast<uint32_t*>(&XL[r * 72 + c4 + 2]) =
            packh2(__float2half_rn(z[2] - __half2float(hh[2])), __float2half_rn(z[3] - __half2float(hh[3])));
    }
    __syncthreads();
    #pragma unroll
    for (int mt = 0; mt < 2; mt++)
        #pragma unroll
        for (int nt = 0; nt < 2; nt++) wmma::fill_fragment(acc[mt][nt], 0.f);
    #pragma unroll
    for (int ks = 0; ks < 4; ks++) {
        #pragma unroll
        for (int mt = 0; mt < 2; mt++) {
            wmma::load_matrix_sync(ah, &XH[(wm * 32 + mt * 16) * 72 + ks * 16], 72);
            wmma::load_matrix_sync(al, &XL[(wm * 32 + mt * 16) * 72 + ks * 16], 72);
            #pragma unroll
            for (int nt = 0; nt < 2; nt++) {
                wmma::load_matrix_sync(bh, &W4H[(wn * 32 + nt * 16) * 72 + ks * 16], 72);
                wmma::load_matrix_sync(bl, &W4L[(wn * 32 + nt * 16) * 72 + ks * 16], 72);
                wmma::mma_sync(acc[mt][nt], ah, bh, acc[mt][nt]);
                wmma::mma_sync(acc[mt][nt], al, bh, acc[mt][nt]);
                wmma::mma_sync(acc[mt][nt], ah, bl, acc[mt][nt]);
            }
        }
    }
    __syncthreads();
    #pragma unroll
    for (int mt = 0; mt < 2; mt++)
        #pragma unroll
        for (int nt = 0; nt < 2; nt++)
            wmma::store_matrix_sync(&FB[(wm * 32 + mt * 16) * 68 + wn * 32 + nt * 16],
                                    acc[mt][nt], 68, wmma::mem_row_major);
    __syncthreads();
    for (int q = 0; q < 8; q++) {
        int g = t + q * 256;
        int r = g >> 4, c4 = (g & 15) * 4;
        float4 v = *reinterpret_cast<float4*>(&FB[r * 68 + c4]);
        float z[4]; __half hh[4];
        float* vp = &v.x;
        #pragma unroll
        for (int qq = 0; qq < 4; qq++) {
            z[qq] = fmaxf(fmaf(vp[qq], BN[128 + c4 + qq], BN[192 + c4 + qq]), 0.f);
            hh[qq] = __float2half_rn(z[qq]);
        }
        size_t o2 = (size_t)(b0 + r) * 8192 + p * 64 + c4;
        *reinterpret_cast<uint2*>(&g_a4h[o2]) =
            make_uint2(packh2(hh[0], hh[1]), packh2(hh[2], hh[3]));
        *reinterpret_cast<uint2*>(&g_a4l[o2]) = make_uint2(
            packh2(__float2half_rn(z[0] - __half2float(hh[0])), __float2half_rn(z[1] - __half2float(hh[1]))),
            packh2(__float2half_rn(z[2] - __half2float(hh[2])), __float2half_rn(z[3] - __half2float(hh[3]))));
    }
}

// ---------------- fc5 via wmma fp16x3, cp.async double-buffered, 512 threads ----------------
// Two 73728B buffers: AH 0, AL 18432, WH 36864, WL 55296 within each.
#define F5_BUF 73728
#define F5_SMEM 147456
__global__ __launch_bounds__(512) void k_fc5_tc(const float* __restrict__ b5,
                                                const float* __restrict__ bn5)
{
    extern __shared__ __align__(16) char smem[];
    float* FB = reinterpret_cast<float*>(smem);             // [128][132] epilogue alias

    int b0 = blockIdx.x * 128, nb = blockIdx.y * 128, t = threadIdx.x;
    int w = t >> 5, wm = w & 3, wn = w >> 2;                 // 16 warps: 4x4 of 32x32 tiles

    FragC acc[2][2];
    FragA ah, al;
    FragB bh, bl;
    #pragma unroll
    for (int mt = 0; mt < 2; mt++)
        #pragma unroll
        for (int nt = 0; nt < 2; nt++) wmma::fill_fragment(acc[mt][nt], 0.f);

    auto issue = [&](int k, int bf) {
        char* B = smem + bf * F5_BUF;
        ldta(g_a4h + (size_t)b0 * 8192 + k * 64, 8192, reinterpret_cast<__half*>(B), t, 512, 128);
        ldta(g_a4l + (size_t)b0 * 8192 + k * 64, 8192, reinterpret_cast<__half*>(B + 18432), t, 512, 128);
        ldta(g_w5h + (size_t)nb * 8192 + k * 64, 8192, reinterpret_cast<__half*>(B + 36864), t, 512, 128);
        ldta(g_w5l + (size_t)nb * 8192 + k * 64, 8192, reinterpret_cast<__half*>(B + 55296), t, 512, 128);
        __pipeline_commit();
    };

    issue(0, 0);
    for (int k = 0; k < 128; k++) {
        if (k + 1 < 128) issue(k + 1, (k + 1) & 1);
        __pipeline_wait_prior((k + 1 < 128) ? 1 : 0);
        __syncthreads();
        char* B = smem + (k & 1) * F5_BUF;
        __half* AH = reinterpret_cast<__half*>(B);
        __half* AL = reinterpret_cast<__half*>(B + 18432);
        __half* WH = reinterpret_cast<__half*>(B + 36864);
        __half* WL = reinterpret_cast<__half*>(B + 55296);
        #pragma unroll
        for (int ks = 0; ks < 4; ks++) {
            #pragma unroll
            for (int mt = 0; mt < 2; mt++) {
                wmma::load_matrix_sync(ah, &AH[(wm * 32 + mt * 16) * 72 + ks * 16], 72);
                wmma::load_matrix_sync(al, &AL[(wm * 32 + mt * 16) * 72 + ks * 16], 72);
                #pragma unroll
                for (int nt = 0; nt < 2; nt++) {
                    wmma::load_matrix_sync(bh, &WH[(wn * 32 + nt * 16) * 72 + ks * 16], 72);
                    wmma::load_matrix_sync(bl, &WL[(wn * 32 + nt * 16) * 72 + ks * 16], 72);
                    wmma::mma_sync(acc[mt][nt], ah, bh, acc[mt][nt]);
                    wmma::mma_sync(acc[mt][nt], al, bh, acc[mt][nt]);
                    wmma::mma_sync(acc[mt][nt], ah, bl, acc[mt][nt]);
                }
            }
        }
        __syncthreads();
    }
    #pragma unroll
    for (int mt = 0; mt < 2; mt++)
        #pragma unroll
        for (int nt = 0; nt < 2; nt++)
            wmma::store_matrix_sync(&FB[(wm * 32 + mt * 16) * 132 + wn * 32 + nt * 16],
                                    acc[mt][nt], 132, wmma::mem_row_major);
    __syncthreads();
    float s5 = bn5[0] * rsqrtf(bn5[3] + EPSF);
    float t5 = bn5[1] - bn5[2] * s5;
    for (int q = 0; q < 8; q++) {
        int g = t + q * 512;
        int r = g >> 5, c4 = (g & 31) * 4;
        float4 v = *reinterpret_cast<float4*>(&FB[r * 132 + c4]);
        float* vp = &v.x;
        #pragma unroll
        for (int qq = 0; qq < 4; qq++)
            vp[qq] = fmaxf(fmaf(vp[qq] + __ldg(&b5[nb + c4 + qq]), s5, t5), 0.f);
        *reinterpret_cast<float4*>(&g_a5[(size_t)(b0 + r) * 512 + nb + c4]) = v;
    }
}

// ---------------- fc6/fc7 fp32 GEMM ----------------
__global__ __launch_bounds__(256) void k_gemm(
    int asel, const float* __restrict__ Wt, const float* __restrict__ bias,
    const float* __restrict__ bn, int N, int K, int relu)
{
    const float* A = asel ? g_a6 : g_a5;
    float* Out = asel ? g_a7 : g_a6;
    __shared__ float As[128 * 33];
    __shared__ float Ws[64 * 33];
    int rb = blockIdx.x * 128, nb = blockIdx.y * 64, t = threadIdx.x;
    int tx = t & 15, ty = t >> 4;
    float acc[8][4];
    #pragma unroll
    for (int ri = 0; ri < 8; ri++)
        #pragma unroll
        for (int ci = 0; ci < 4; ci++) acc[ri][ci] = 0.f;
    for (int k0 = 0; k0 < K; k0 += 32) {
        for (int i = t; i < 4096; i += 256)
            As[(i >> 5) * 33 + (i & 31)] = A[(size_t)(rb + (i >> 5)) * K + k0 + (i & 31)];
        for (int i = t; i < 2048; i += 256)
            Ws[(i >> 5) * 33 + (i & 31)] = Wt[(size_t)(nb + (i >> 5)) * K + k0 + (i & 31)];
        __syncthreads();
        #pragma unroll 4
        for (int c = 0; c < 32; c++) {
            float a[8], ww[4];
            #pragma unroll
            for (int ri = 0; ri < 8; ri++) a[ri] = As[(ty * 8 + ri) * 33 + c];
            #pragma unroll
            for (int ci = 0; ci < 4; ci++) ww[ci] = Ws[(tx * 4 + ci) * 33 + c];
            #pragma unroll
            for (int ri = 0; ri < 8; ri++)
                #pragma unroll
                for (int ci = 0; ci < 4; ci++) acc[ri][ci] = fmaf(a[ri], ww[ci], acc[ri][ci]);
        }
        __syncthreads();
    }
    float s = bn[0] * rsqrtf(bn[3] + EPSF);
    float tt = bn[1] - bn[2] * s;
    float bv[4];
    #pragma unroll
    for (int ci = 0; ci < 4; ci++) bv[ci] = bias[nb + tx * 4 + ci];
    #pragma unroll
    for (int ri = 0; ri < 8; ri++) {
        float z[4];
        #pragma unroll
        for (int ci = 0; ci < 4; ci++) {
            z[ci] = fmaf(acc[ri][ci] + bv[ci], s, tt);
            if (relu) z[ci] = fmaxf(z[ci], 0.f);
        }
        *reinterpret_cast<float4*>(&Out[(size_t)(rb + ty * 8 + ri) * N + nb + tx * 4]) =
            make_float4(z[0], z[1], z[2], z[3]);
    }
}

__global__ __launch_bounds__(256) void k_fc8(const float* __restrict__ w8,
                                             const float* __restrict__ b8,
                                             float* __restrict__ out)
{
    int t = threadIdx.x;
    int b = blockIdx.x * 32 + (t >> 3), n = t & 7;
    const float* ar = &g_a7[b * 128];
    const float* wr = &w8[n * 128];
    float acc = 0.f;
    #pragma unroll 8
    for (int k = 0; k < 128; k++) acc = fmaf(ar[k], wr[k], acc);
    out[b * 8 + n] = acc + b8[n];
}

// ---------------- launch ----------------
extern "C" void kernel_launch(void* const* d_in, const int* in_sizes, int n_in,
                              void* d_out, int out_size)
{
    const float* x   = (const float*)d_in[0];
    const float* bn0 = (const float*)d_in[1];
    const float* w1  = (const float*)d_in[2];
    const float* b1  = (const float*)d_in[3];
    const float* bn1 = (const float*)d_in[4];
    const float* w2  = (const float*)d_in[5];
    const float* b2  = (const float*)d_in[6];
    const float* bn2 = (const float*)d_in[7];
    const float* w3  = (const float*)d_in[8];
    const float* bn3 = (const float*)d_in[9];
    const float* w4  = (const float*)d_in[10];
    const float* bn4 = (const float*)d_in[11];
    const float* w5  = (const float*)d_in[12];
    const float* b5  = (const float*)d_in[13];
    const float* bn5 = (const float*)d_in[14];
    const float* w6  = (const float*)d_in[15];
    const float* b6  = (const float*)d_in[16];
    const float* bn6 = (const float*)d_in[17];
    const float* w7  = (const float*)d_in[18];
    const float* b7  = (const float*)d_in[19];
    const float* bn7 = (const float*)d_in[20];
    const float* w8  = (const float*)d_in[21];
    const float* b8  = (const float*)d_in[22];
    float* out = (float*)d_out;

    cudaFuncSetAttribute(k_conv2,  cudaFuncAttributeMaxDynamicSharedMemorySize, C2_SMEM);
    cudaFuncSetAttribute(k_lc_tc,  cudaFuncAttributeMaxDynamicSharedMemorySize, LC_SMEM);
    cudaFuncSetAttribute(k_fc5_tc, cudaFuncAttributeMaxDynamicSharedMemorySize, F5_SMEM);

    k_prep_w2 <<<144,   256>>>(w2);
    k_prep_w34<<<4096,  256>>>(w3, w4);
    k_prep_w5 <<<16384, 256>>>(w5);

    k_conv1<<<8192, 256>>>(x, bn0, w1, b1, bn1);
    k_conv2<<<dim3(128, 64), 256, C2_SMEM>>>(b2, bn2);
    k_lc_tc<<<dim3(64, 128), 256, LC_SMEM>>>(bn3, bn4);
    k_fc5_tc<<<dim3(64, 4), 512, F5_SMEM>>>(b5, bn5);
    k_gemm<<<dim3(64, 8), 256>>>(0, w6, b6, bn6, 512, 512, 1);
    k_gemm<<<dim3(64, 2), 256>>>(1, w7, b7, bn7, 128, 512, 1);
    k_fc8<<<256, 256>>>(w8, b8, out);
}

// round 11
// speedup vs baseline: 3.2436x; 1.0391x over previous
#include <cuda_runtime.h>
#include <cuda_fp16.h>
#include <cuda_pipeline.h>
#include <mma.h>
#include <cstdint>
using namespace nvcuda;
#define EPSF 1e-5f
// B=8192, C=64, H=8, W=16, P=128, F5=8192

// ---------------- scratch ----------------
__device__ __half g_w2th[36864], g_w2tl[36864];         // conv2 w [tap][o][c] hi/lo
__device__ __half g_w3h[524288], g_w3l[524288];         // lc3 w [p][o][c] hi/lo
__device__ __half g_w4h[524288], g_w4l[524288];         // lc4 w [p][o][c] hi/lo
__device__ __half g_w5h[4194304], g_w5l[4194304];       // fc5 w [n][p*64+c] hi/lo
__device__ __half g_w6h[262144],  g_w6l[262144];        // fc6 w [n][k] hi/lo
__device__ __half g_w7h[65536],   g_w7l[65536];         // fc7 w [n][k] hi/lo
__device__ __half g_a1h[67108864], g_a1l[67108864];     // conv1 out [p][b][c] hi/lo
__device__ __half g_a4h[67108864], g_a4l[67108864];     // lc4 out [b][p*64+c] hi/lo
__device__ __half g_a5h[4194304], g_a5l[4194304];       // fc5 out hi/lo
__device__ __half g_a6h[4194304], g_a6l[4194304];       // fc6 out hi/lo
__device__ float  g_a7[1048576];                        // fc7 out f32

__device__ __forceinline__ uint32_t packh2(__half a, __half b) {
    __half2 h = __halves2half2(a, b);
    return *reinterpret_cast<uint32_t*>(&h);
}
// async load [rows x 64 halves] tile into smem rows of 72 halves (pad)
__device__ __forceinline__ void ldta(const __half* __restrict__ src, size_t rowStride,
                                     __half* dst, int t, int nt, int rows) {
    for (int i = t; i < rows * 8; i += nt) {
        int r = i >> 3, c = i & 7;
        __pipeline_memcpy_async(&dst[r * 72 + c * 8], &src[(size_t)r * rowStride + c * 8], 16);
    }
}

typedef wmma::fragment<wmma::matrix_a, 16,16,16, __half, wmma::row_major> FragA;
typedef wmma::fragment<wmma::matrix_b, 16,16,16, __half, wmma::col_major> FragB;
typedef wmma::fragment<wmma::accumulator, 16,16,16, float> FragC;

// ---------------- weight prep ----------------
__global__ void k_prep_w2(const float* __restrict__ w2) {
    int idx = blockIdx.x * 256 + threadIdx.x;
    if (idx >= 36864) return;
    int o = idx / 576, r = idx % 576;                    // in: [o][c][tap]
    int c = r / 9, tap = r % 9;
    float v = w2[idx];
    __half h = __float2half_rn(v);
    int d = tap * 4096 + o * 64 + c;                     // out: [tap][o][c]
    g_w2th[d] = h; g_w2tl[d] = __float2half_rn(v - __half2float(h));
}
__global__ void k_prep_w34(const float* __restrict__ w3, const float* __restrict__ w4) {
    int idx = blockIdx.x * 256 + threadIdx.x;            // 1048576
    int sel = idx >> 19, i = idx & 524287;
    int o = i >> 13, c = (i >> 7) & 63, p = i & 127;
    float v = sel ? w4[i] : w3[i];
    __half h = __float2half_rn(v), l = __float2half_rn(v - __half2float(h));
    int d = p * 4096 + o * 64 + c;
    if (sel) { g_w4h[d] = h; g_w4l[d] = l; } else { g_w3h[d] = h; g_w3l[d] = l; }
}
__global__ void k_prep_w5(const float* __restrict__ w5) {
    int idx = blockIdx.x * 256 + threadIdx.x;            // 4194304
    int n = idx >> 13, k = idx & 8191;
    int c = k >> 7, p = k & 127;
    float v = w5[idx];
    __half h = __float2half_rn(v);
    int d = n * 8192 + p * 64 + c;
    g_w5h[d] = h; g_w5l[d] = __float2half_rn(v - __half2float(h));
}
__global__ void k_prep_w67(const float* __restrict__ w6, const float* __restrict__ w7) {
    int idx = blockIdx.x * 256 + threadIdx.x;            // 327680
    if (idx >= 327680) return;
    if (idx < 262144) {
        float v = w6[idx];
        __half h = __float2half_rn(v);
        g_w6h[idx] = h; g_w6l[idx] = __float2half_rn(v - __half2float(h));
    } else {
        int d = idx - 262144;
        float v = w7[d];
        __half h = __float2half_rn(v);
        g_w7h[d] = h; g_w7l[d] = __float2half_rn(v - __half2float(h));
    }
}

// ---------------- conv1: bn0 + conv1 + bn1 + relu -> g_a1 hi/lo [p][b][c] ----------------
__global__ __launch_bounds__(256) void k_conv1(
    const float* __restrict__ x, const float* __restrict__ bn0,
    const float* __restrict__ w1, const float* __restrict__ b1,
    const float* __restrict__ bn1)
{
    __shared__ float h0s[180];
    __shared__ float w1s[576];
    __shared__ float s1s[64], t1s[64];
    int b = blockIdx.x, t = threadIdx.x;
    if (t < 180) h0s[t] = 0.f;
    for (int i = t; i < 576; i += 256) w1s[i] = w1[i];
    if (t < 64) {
        float s = bn1[t] * rsqrtf(bn1[192 + t] + EPSF);
        s1s[t] = s;
        t1s[t] = bn1[64 + t] - bn1[128 + t] * s + b1[t] * s;   // fold bias
    }
    __syncthreads();
    if (t < 128) {
        float s0 = bn0[0] * rsqrtf(bn0[3] + EPSF);
        float t0 = bn0[1] - bn0[2] * s0;
        int i = t >> 4, j = t & 15;
        h0s[(i + 1) * 18 + (j + 1)] = x[b * 128 + j * 8 + i] * s0 + t0;
    }
    __syncthreads();
    for (int idx = t; idx < 2048; idx += 256) {
        int p = idx >> 4, o4 = (idx & 15) << 2;
        int i = p >> 4, j = p & 15;
        __half hh[4], ll[4];
        #pragma unroll
        for (int q = 0; q < 4; q++) {
            int o = o4 + q;
            float acc = 0.f;
            #pragma unroll
            for (int di = 0; di < 3; di++)
                #pragma unroll
                for (int dj = 0; dj < 3; dj++)
                    acc = fmaf(h0s[(i + di) * 18 + (j + dj)], w1s[o * 9 + di * 3 + dj], acc);
            float z = fmaxf(fmaf(acc, s1s[o], t1s[o]), 0.f);
            hh[q] = __float2half_rn(z);
            ll[q] = __float2half_rn(z - __half2float(hh[q]));
        }
        size_t d = (size_t)p * 524288 + (size_t)b * 64 + o4;
        *reinterpret_cast<uint2*>(&g_a1h[d]) = make_uint2(packh2(hh[0], hh[1]), packh2(hh[2], hh[3]));
        *reinterpret_cast<uint2*>(&g_a1l[d]) = make_uint2(packh2(ll[0], ll[1]), packh2(ll[2], ll[3]));
    }
}

// ---------------- fused conv2 + lc3 + lc4 (wmma fp16x3, all chained in smem) ----------------
// grid (128 pixels, 64 btiles of 128), 256 threads (8 warps, warp tile 32x32).
#define CL_T1  55296
#define CL_W3H 110592
#define CL_W3L 119808
#define CL_W4H 129024
#define CL_W4L 138240
#define CL_BN  147456
#define CL_SMEM 148992
__global__ __launch_bounds__(256) void k_c2lc(
    const float* __restrict__ b2,  const float* __restrict__ bn2,
    const float* __restrict__ bn3, const float* __restrict__ bn4)
{
    extern __shared__ __align__(16) char smem[];
    float*  FB  = reinterpret_cast<float*>(smem);                 // [128][68] alias of T0
    __half* XH  = reinterpret_cast<__half*>(smem + CL_T1);
    __half* XL  = reinterpret_cast<__half*>(smem + CL_T1 + 18432);
    __half* W3H = reinterpret_cast<__half*>(smem + CL_W3H);
    __half* W3L = reinterpret_cast<__half*>(smem + CL_W3L);
    __half* W4H = reinterpret_cast<__half*>(smem + CL_W4H);
    __half* W4L = reinterpret_cast<__half*>(smem + CL_W4L);
    float*  BN  = reinterpret_cast<float*>(smem + CL_BN);

    int p = blockIdx.x, b0 = blockIdx.y * 128, t = threadIdx.x;
    int w = t >> 5, wm = w & 3, wn = w >> 2;
    int i = p >> 4, j = p & 15;

    if (t < 64) {
        float s = bn2[t] * rsqrtf(bn2[192 + t] + EPSF);
        BN[t] = s;       BN[64 + t]  = bn2[64 + t] - bn2[128 + t] * s + b2[t] * s;
        s = bn3[t] * rsqrtf(bn3[192 + t] + EPSF);
        BN[128 + t] = s; BN[192 + t] = bn3[64 + t] - bn3[128 + t] * s;
        s = bn4[t] * rsqrtf(bn4[192 + t] + EPSF);
        BN[256 + t] = s; BN[320 + t] = bn4[64 + t] - bn4[128 + t] * s;
    }

    // G0: lc weights (independent of conv2 taps)
    ldta(g_w3h + p * 4096, 64, W3H, t, 256, 64);
    ldta(g_w3l + p * 4096, 64, W3L, t, 256, 64);
    ldta(g_w4h + p * 4096, 64, W4H, t, 256, 64);
    ldta(g_w4l + p * 4096, 64, W4L, t, 256, 64);
    __pipeline_commit();

    int vt[9], nv = 0;
    #pragma unroll
    for (int tap = 0; tap < 9; tap++) {
        int ii = i + tap / 3 - 1, jj = j + tap % 3 - 1;
        if (ii >= 0 && ii < 8 && jj >= 0 && jj < 16) vt[nv++] = tap;
    }

    FragC acc[2][2];
    FragA ah, al;
    #pragma unroll
    for (int mt = 0; mt < 2; mt++)
        #pragma unroll
        for (int nt = 0; nt < 2; nt++) wmma::fill_fragment(acc[mt][nt], 0.f);

    auto issue = [&](int q, int bf) {
        int tap = vt[q];
        int pp = (i + tap / 3 - 1) * 16 + (j + tap % 3 - 1);
        char* B = smem + bf * 55296;
        size_t ab = (size_t)pp * 524288 + (size_t)b0 * 64;
        ldta(g_a1h + ab, 64, reinterpret_cast<__half*>(B), t, 256, 128);
        ldta(g_a1l + ab, 64, reinterpret_cast<__half*>(B + 18432), t, 256, 128);
        ldta(g_w2th + tap * 4096, 64, reinterpret_cast<__half*>(B + 36864), t, 256, 64);
        ldta(g_w2tl + tap * 4096, 64, reinterpret_cast<__half*>(B + 46080), t, 256, 64);
        __pipeline_commit();
    };

    issue(0, 0);
    for (int q = 0; q < nv; q++) {
        if (q + 1 < nv) issue(q + 1, (q + 1) & 1);
        __pipeline_wait_prior((q + 1 < nv) ? 1 : 0);
        __syncthreads();
        char* B = smem + (q & 1) * 55296;
        __half* AH = reinterpret_cast<__half*>(B);
        __half* AL = reinterpret_cast<__half*>(B + 18432);
        __half* WH = reinterpret_cast<__half*>(B + 36864);
        __half* WL = reinterpret_cast<__half*>(B + 46080);
        #pragma unroll
        for (int ks = 0; ks < 4; ks++) {
            FragB bhf[2], blf[2];
            #pragma unroll
            for (int nt = 0; nt < 2; nt++) {
                wmma::load_matrix_sync(bhf[nt], &WH[(wn * 32 + nt * 16) * 72 + ks * 16], 72);
                wmma::load_matrix_sync(blf[nt], &WL[(wn * 32 + nt * 16) * 72 + ks * 16], 72);
            }
            #pragma unroll
            for (int mt = 0; mt < 2; mt++) {
                wmma::load_matrix_sync(ah, &AH[(wm * 32 + mt * 16) * 72 + ks * 16], 72);
                wmma::load_matrix_sync(al, &AL[(wm * 32 + mt * 16) * 72 + ks * 16], 72);
                #pragma unroll
                for (int nt = 0; nt < 2; nt++) {
                    wmma::mma_sync(acc[mt][nt], ah, bhf[nt], acc[mt][nt]);
                    wmma::mma_sync(acc[mt][nt], al, bhf[nt], acc[mt][nt]);
                    wmma::mma_sync(acc[mt][nt], ah, blf[nt], acc[mt][nt]);
                }
            }
        }
        __syncthreads();
    }

    // ---- conv2 epilogue -> XH/XL ----
    #pragma unroll
    for (int mt = 0; mt < 2; mt++)
        #pragma unroll
        for (int nt = 0; nt < 2; nt++)
            wmma::store_matrix_sync(&FB[(wm * 32 + mt * 16) * 68 + wn * 32 + nt * 16],
                                    acc[mt][nt], 68, wmma::mem_row_major);
    __syncthreads();
    for (int q = 0; q < 8; q++) {
        int g = t + q * 256;
        int r = g >> 4, c4 = (g & 15) * 4;
        float4 v = *reinterpret_cast<float4*>(&FB[r * 68 + c4]);
        float z[4]; __half hh[4];
        float* vp = &v.x;
        #pragma unroll
        for (int qq = 0; qq < 4; qq++) {
            z[qq] = fmaxf(fmaf(vp[qq], BN[c4 + qq], BN[64 + c4 + qq]), 0.f);
            hh[qq] = __float2half_rn(z[qq]);
        }
        *reinterpret_cast<uint32_t*>(&XH[r * 72 + c4])     = packh2(hh[0], hh[1]);
        *reinterpret_cast<uint32_t*>(&XH[r * 72 + c4 + 2]) = packh2(hh[2], hh[3]);
        *reinterpret_cast<uint32_t*>(&XL[r * 72 + c4]) =
            packh2(__float2half_rn(z[0] - __half2float(hh[0])), __float2half_rn(z[1] - __half2float(hh[1])));
        *reinterpret_cast<uint32_t*>(&XL[r * 72 + c4 + 2]) =
            packh2(__float2half_rn(z[2] - __half2float(hh[2])), __float2half_rn(z[3] - __half2float(hh[3])));
    }
    __syncthreads();

    // ---- lc3 ----
    #pragma unroll
    for (int mt = 0; mt < 2; mt++)
        #pragma unroll
        for (int nt = 0; nt < 2; nt++) wmma::fill_fragment(acc[mt][nt], 0.f);
    #pragma unroll
    for (int ks = 0; ks < 4; ks++) {
        FragB bhf[2], blf[2];
        #pragma unroll
        for (int nt = 0; nt < 2; nt++) {
            wmma::load_matrix_sync(bhf[nt], &W3H[(wn * 32 + nt * 16) * 72 + ks * 16], 72);
            wmma::load_matrix_sync(blf[nt], &W3L[(wn * 32 + nt * 16) * 72 + ks * 16], 72);
        }
        #pragma unroll
        for (int mt = 0; mt < 2; mt++) {
            wmma::load_matrix_sync(ah, &XH[(wm * 32 + mt * 16) * 72 + ks * 16], 72);
            wmma::load_matrix_sync(al, &XL[(wm * 32 + mt * 16) * 72 + ks * 16], 72);
            #pragma unroll
            for (int nt = 0; nt < 2; nt++) {
                wmma::mma_sync(acc[mt][nt], ah, bhf[nt], acc[mt][nt]);
                wmma::mma_sync(acc[mt][nt], al, bhf[nt], acc[mt][nt]);
                wmma::mma_sync(acc[mt][nt], ah, blf[nt], acc[mt][nt]);
            }
        }
    }
    #pragma unroll
    for (int mt = 0; mt < 2; mt++)
        #pragma unroll
        for (int nt = 0; nt < 2; nt++)
            wmma::store_matrix_sync(&FB[(wm * 32 + mt * 16) * 68 + wn * 32 + nt * 16],
                                    acc[mt][nt], 68, wmma::mem_row_major);
    __syncthreads();
    for (int q = 0; q < 8; q++) {
        int g = t + q * 256;
        int r = g >> 4, c4 = (g & 15) * 4;
        float4 v = *reinterpret_cast<float4*>(&FB[r * 68 + c4]);
        float z[4]; __half hh[4];
        float* vp = &v.x;
        #pragma unroll
        for (int qq = 0; qq < 4; qq++) {
            z[qq] = fmaxf(fmaf(vp[qq], BN[128 + c4 + qq], BN[192 + c4 + qq]), 0.f);
            hh[qq] = __float2half_rn(z[qq]);
        }
        *reinterpret_cast<uint32_t*>(&XH[r * 72 + c4])     = packh2(hh[0], hh[1]);
        *reinterpret_cast<uint32_t*>(&XH[r * 72 + c4 + 2]) = packh2(hh[2], hh[3]);
        *reinterpret_cast<uint32_t*>(&XL[r * 72 + c4]) =
            packh2(__float2half_rn(z[0] - __half2float(hh[0])), __float2half_rn(z[1] - __half2float(hh[1])));
        *reinterpret_cast<uint32_t*>(&XL[r * 72 + c4 + 2]) =
            packh2(__float2half_rn(z[2] - __half2float(hh[2])), __float2half_rn(z[3] - __half2float(hh[3])));
    }
    __syncthreads();

    // ---- lc4 ----
    #pragma unroll
    for (int mt = 0; mt < 2; mt++)
        #pragma unroll
        for (int nt = 0; nt < 2; nt++) wmma::fill_fragment(acc[mt][nt], 0.f);
    #pragma unroll
    for (int ks = 0; ks < 4; ks++) {
        FragB bhf[2], blf[2];
        #pragma unroll
        for (int nt = 0; nt < 2; nt++) {
            wmma::load_matrix_sync(bhf[nt], &W4H[(wn * 32 + nt * 16) * 72 + ks * 16], 72);
            wmma::load_matrix_sync(blf[nt], &W4L[(wn * 32 + nt * 16) * 72 + ks * 16], 72);
        }
        #pragma unroll
        for (int mt = 0; mt < 2; mt++) {
            wmma::load_matrix_sync(ah, &XH[(wm * 32 + mt * 16) * 72 + ks * 16], 72);
            wmma::load_matrix_sync(al, &XL[(wm * 32 + mt * 16) * 72 + ks * 16], 72);
            #pragma unroll
            for (int nt = 0; nt < 2; nt++) {
                wmma::mma_sync(acc[mt][nt], ah, bhf[nt], acc[mt][nt]);
                wmma::mma_sync(acc[mt][nt], al, bhf[nt], acc[mt][nt]);
                wmma::mma_sync(acc[mt][nt], ah, blf[nt], acc[mt][nt]);
            }
        }
    }
    #pragma unroll
    for (int mt = 0; mt < 2; mt++)
        #pragma unroll
        for (int nt = 0; nt < 2; nt++)
            wmma::store_matrix_sync(&FB[(wm * 32 + mt * 16) * 68 + wn * 32 + nt * 16],
                                    acc[mt][nt], 68, wmma::mem_row_major);
    __syncthreads();
    for (int q = 0; q < 8; q++) {
        int g = t + q * 256;
        int r = g >> 4, c4 = (g & 15) * 4;
        float4 v = *reinterpret_cast<float4*>(&FB[r * 68 + c4]);
        float z[4]; __half hh[4];
        float* vp = &v.x;
        #pragma unroll
        for (int qq = 0; qq < 4; qq++) {
            z[qq] = fmaxf(fmaf(vp[qq], BN[256 + c4 + qq], BN[320 + c4 + qq]), 0.f);
            hh[qq] = __float2half_rn(z[qq]);
        }
        size_t o2 = (size_t)(b0 + r) * 8192 + p * 64 + c4;
        *reinterpret_cast<uint2*>(&g_a4h[o2]) =
            make_uint2(packh2(hh[0], hh[1]), packh2(hh[2], hh[3]));
        *reinterpret_cast<uint2*>(&g_a4l[o2]) = make_uint2(
            packh2(__float2half_rn(z[0] - __half2float(hh[0])), __float2half_rn(z[1] - __half2float(hh[1]))),
            packh2(__float2half_rn(z[2] - __half2float(hh[2])), __float2half_rn(z[3] - __half2float(hh[3]))));
    }
}

// ---------------- generic wmma fc layer (fc5/fc6/fc7), cp.async double-buffered ----------------
// sel: 0 = fc5 (a4->a5 h/l, K=8192), 1 = fc6 (a5->a6 h/l, K=512), 2 = fc7 (a6->a7 f32, K=512, N=128)
#define FC_BUF 73728
#define FC_SMEM 147456
__global__ __launch_bounds__(512) void k_fcw(int sel, const float* __restrict__ bias,
                                             const float* __restrict__ bn)
{
    extern __shared__ __align__(16) char smem[];
    float* FB = reinterpret_cast<float*>(smem);             // [128][132]

    const __half *Ah, *Al, *Wh, *Wl;
    __half *Oh = nullptr, *Ol = nullptr;
    float *Of = nullptr;
    int K;
    if (sel == 0)      { Ah = g_a4h; Al = g_a4l; Wh = g_w5h; Wl = g_w5l; Oh = g_a5h; Ol = g_a5l; K = 8192; }
    else if (sel == 1) { Ah = g_a5h; Al = g_a5l; Wh = g_w6h; Wl = g_w6l; Oh = g_a6h; Ol = g_a6l; K = 512; }
    else               { Ah = g_a6h; Al = g_a6l; Wh = g_w7h; Wl = g_w7l; Of = g_a7; K = 512; }
    int N = (sel == 2) ? 128 : 512;
    int nch = K >> 6;

    int b0 = blockIdx.x * 128, nb = blockIdx.y * 128, t = threadIdx.x;
    int w = t >> 5, wm = w & 3, wn = w >> 2;                 // 16 warps: 4x4 of 32x32

    FragC acc[2][2];
    FragA ah, al;
    #pragma unroll
    for (int mt = 0; mt < 2; mt++)
        #pragma unroll
        for (int nt = 0; nt < 2; nt++) wmma::fill_fragment(acc[mt][nt], 0.f);

    auto issue = [&](int k, int bf) {
        char* B = smem + bf * FC_BUF;
        ldta(Ah + (size_t)b0 * K + k * 64, K, reinterpret_cast<__half*>(B), t, 512, 128);
        ldta(Al + (size_t)b0 * K + k * 64, K, reinterpret_cast<__half*>(B + 18432), t, 512, 128);
        ldta(Wh + (size_t)nb * K + k * 64, K, reinterpret_cast<__half*>(B + 36864), t, 512, 128);
        ldta(Wl + (size_t)nb * K + k * 64, K, reinterpret_cast<__half*>(B + 55296), t, 512, 128);
        __pipeline_commit();
    };

    issue(0, 0);
    for (int k = 0; k < nch; k++) {
        if (k + 1 < nch) issue(k + 1, (k + 1) & 1);
        __pipeline_wait_prior((k + 1 < nch) ? 1 : 0);
        __syncthreads();
        char* B = smem + (k & 1) * FC_BUF;
        __half* AH = reinterpret_cast<__half*>(B);
        __half* AL = reinterpret_cast<__half*>(B + 18432);
        __half* WH = reinterpret_cast<__half*>(B + 36864);
        __half* WL = reinterpret_cast<__half*>(B + 55296);
        #pragma unroll
        for (int ks = 0; ks < 4; ks++) {
            FragB bhf[2], blf[2];
            #pragma unroll
            for (int nt = 0; nt < 2; nt++) {
                wmma::load_matrix_sync(bhf[nt], &WH[(wn * 32 + nt * 16) * 72 + ks * 16], 72);
                wmma::load_matrix_sync(blf[nt], &WL[(wn * 32 + nt * 16) * 72 + ks * 16], 72);
            }
            #pragma unroll
            for (int mt = 0; mt < 2; mt++) {
                wmma::load_matrix_sync(ah, &AH[(wm * 32 + mt * 16) * 72 + ks * 16], 72);
                wmma::load_matrix_sync(al, &AL[(wm * 32 + mt * 16) * 72 + ks * 16], 72);
                #pragma unroll
                for (int nt = 0; nt < 2; nt++) {
                    wmma::mma_sync(acc[mt][nt], ah, bhf[nt], acc[mt][nt]);
                    wmma::mma_sync(acc[mt][nt], al, bhf[nt], acc[mt][nt]);
                    wmma::mma_sync(acc[mt][nt], ah, blf[nt], acc[mt][nt]);
                }
            }
        }
        __syncthreads();
    }
    #pragma unroll
    for (int mt = 0; mt < 2; mt++)
        #pragma unroll
        for (int nt = 0; nt < 2; nt++)
            wmma::store_matrix_sync(&FB[(wm * 32 + mt * 16) * 132 + wn * 32 + nt * 16],
                                    acc[mt][nt], 132, wmma::mem_row_major);
    __syncthreads();
    float s = bn[0] * rsqrtf(bn[3] + EPSF);
    float tt = bn[1] - bn[2] * s;
    for (int q = 0; q < 8; q++) {
        int g = t + q * 512;
        int r = g >> 5, c4 = (g & 31) * 4;
        float4 v = *reinterpret_cast<float4*>(&FB[r * 132 + c4]);
        float* vp = &v.x;
        float z[4];
        #pragma unroll
        for (int qq = 0; qq < 4; qq++)
            z[qq] = fmaxf(fmaf(vp[qq] + __ldg(&bias[nb + c4 + qq]), s, tt), 0.f);
        if (Of) {
            *reinterpret_cast<float4*>(&Of[(size_t)(b0 + r) * N + nb + c4]) =
                make_float4(z[0], z[1], z[2], z[3]);
        } else {
            __half hh[4];
            #pragma unroll
            for (int qq = 0; qq < 4; qq++) hh[qq] = __float2half_rn(z[qq]);
            size_t o2 = (size_t)(b0 + r) * 512 + nb + c4;
            *reinterpret_cast<uint2*>(&Oh[o2]) =
                make_uint2(packh2(hh[0], hh[1]), packh2(hh[2], hh[3]));
            *reinterpret_cast<uint2*>(&Ol[o2]) = make_uint2(
                packh2(__float2half_rn(z[0] - __half2float(hh[0])), __float2half_rn(z[1] - __half2float(hh[1]))),
                packh2(__float2half_rn(z[2] - __half2float(hh[2])), __float2half_rn(z[3] - __half2float(hh[3]))));
        }
    }
}

// ---------------- fc8: (B,128) @ (8,128)^T + b8 -> d_out ----------------
__global__ __launch_bounds__(256) void k_fc8(const float* __restrict__ w8,
                                             const float* __restrict__ b8,
                                             float* __restrict__ out)
{
    int t = threadIdx.x;
    int b = blockIdx.x * 32 + (t >> 3), n = t & 7;
    const float* ar = &g_a7[b * 128];
    const float* wr = &w8[n * 128];
    float acc = 0.f;
    #pragma unroll 8
    for (int k = 0; k < 128; k++) acc = fmaf(ar[k], wr[k], acc);
    out[b * 8 + n] = acc + b8[n];
}

// ---------------- launch ----------------
extern "C" void kernel_launch(void* const* d_in, const int* in_sizes, int n_in,
                              void* d_out, int out_size)
{
    const float* x   = (const float*)d_in[0];
    const float* bn0 = (const float*)d_in[1];
    const float* w1  = (const float*)d_in[2];
    const float* b1  = (const float*)d_in[3];
    const float* bn1 = (const float*)d_in[4];
    const float* w2  = (const float*)d_in[5];
    const float* b2  = (const float*)d_in[6];
    const float* bn2 = (const float*)d_in[7];
    const float* w3  = (const float*)d_in[8];
    const float* bn3 = (const float*)d_in[9];
    const float* w4  = (const float*)d_in[10];
    const float* bn4 = (const float*)d_in[11];
    const float* w5  = (const float*)d_in[12];
    const float* b5  = (const float*)d_in[13];
    const float* bn5 = (const float*)d_in[14];
    const float* w6  = (const float*)d_in[15];
    const float* b6  = (const float*)d_in[16];
    const float* bn6 = (const float*)d_in[17];
    const float* w7  = (const float*)d_in[18];
    const float* b7  = (const float*)d_in[19];
    const float* bn7 = (const float*)d_in[20];
    const float* w8  = (const float*)d_in[21];
    const float* b8  = (const float*)d_in[22];
    float* out = (float*)d_out;

    cudaFuncSetAttribute(k_c2lc, cudaFuncAttributeMaxDynamicSharedMemorySize, CL_SMEM);
    cudaFuncSetAttribute(k_fcw,  cudaFuncAttributeMaxDynamicSharedMemorySize, FC_SMEM);

    k_prep_w2 <<<144,   256>>>(w2);
    k_prep_w34<<<4096,  256>>>(w3, w4);
    k_prep_w5 <<<16384, 256>>>(w5);
    k_prep_w67<<<1280,  256>>>(w6, w7);

    k_conv1<<<8192, 256>>>(x, bn0, w1, b1, bn1);
    k_c2lc<<<dim3(128, 64), 256, CL_SMEM>>>(b2, bn2, bn3, bn4);
    k_fcw<<<dim3(64, 4), 512, FC_SMEM>>>(0, b5, bn5);
    k_fcw<<<dim3(64, 4), 512, FC_SMEM>>>(1, b6, bn6);
    k_fcw<<<dim3(64, 1), 512, FC_SMEM>>>(2, b7, bn7);
    k_fc8<<<256, 256>>>(w8, b8, out);
}

// round 12
// speedup vs baseline: 4.3544x; 1.3424x over previous
#include <cuda_runtime.h>
#include <cuda_fp16.h>
#include <cuda_pipeline.h>
#include <mma.h>
#include <cstdint>
using namespace nvcuda;
#define EPSF 1e-5f
// B=8192, C=64, H=8, W=16, P=128, F5=8192

// ---------------- scratch ----------------
__device__ __half g_w2th[36864], g_w2tl[36864];         // conv2 w [tap][o][c] hi/lo
__device__ __half g_w3h[524288], g_w3l[524288];         // lc3 w [p][o][c] hi/lo
__device__ __half g_w4h[524288], g_w4l[524288];         // lc4 w [p][o][c] hi/lo
__device__ __half g_w5h[4194304], g_w5l[4194304];       // fc5 w [n][p*64+c] hi/lo
__device__ __half g_w6h[262144],  g_w6l[262144];        // fc6 w [n][k] hi/lo
__device__ __half g_w7h[65536],   g_w7l[65536];         // fc7 w [n][k] hi/lo
__device__ __half g_a1h[67108864];                      // conv1 out [p][b][c] fp16
__device__ __half g_a4h[67108864];                      // lc4 out [b][p*64+c] fp16
__device__ __half g_a5h[4194304];                       // fc5 out fp16
__device__ __half g_a6h[4194304];                       // fc6 out fp16
__device__ float  g_a7[1048576];                        // fc7 out f32

__device__ __forceinline__ uint32_t packh2(__half a, __half b) {
    __half2 h = __halves2half2(a, b);
    return *reinterpret_cast<uint32_t*>(&h);
}
// async load [rows x 64 halves] tile into smem rows of 72 halves (pad)
__device__ __forceinline__ void ldta(const __half* __restrict__ src, size_t rowStride,
                                     __half* dst, int t, int nt, int rows) {
    for (int i = t; i < rows * 8; i += nt) {
        int r = i >> 3, c = i & 7;
        __pipeline_memcpy_async(&dst[r * 72 + c * 8], &src[(size_t)r * rowStride + c * 8], 16);
    }
}

typedef wmma::fragment<wmma::matrix_a, 16,16,16, __half, wmma::row_major> FragA;
typedef wmma::fragment<wmma::matrix_b, 16,16,16, __half, wmma::col_major> FragB;
typedef wmma::fragment<wmma::accumulator, 16,16,16, float> FragC;

// ---------------- weight prep ----------------
__global__ void k_prep_w2(const float* __restrict__ w2) {
    int idx = blockIdx.x * 256 + threadIdx.x;
    if (idx >= 36864) return;
    int o = idx / 576, r = idx % 576;                    // in: [o][c][tap]
    int c = r / 9, tap = r % 9;
    float v = w2[idx];
    __half h = __float2half_rn(v);
    int d = tap * 4096 + o * 64 + c;                     // out: [tap][o][c]
    g_w2th[d] = h; g_w2tl[d] = __float2half_rn(v - __half2float(h));
}
__global__ void k_prep_w34(const float* __restrict__ w3, const float* __restrict__ w4) {
    int idx = blockIdx.x * 256 + threadIdx.x;            // 1048576
    int sel = idx >> 19, i = idx & 524287;
    int o = i >> 13, c = (i >> 7) & 63, p = i & 127;
    float v = sel ? w4[i] : w3[i];
    __half h = __float2half_rn(v), l = __float2half_rn(v - __half2float(h));
    int d = p * 4096 + o * 64 + c;
    if (sel) { g_w4h[d] = h; g_w4l[d] = l; } else { g_w3h[d] = h; g_w3l[d] = l; }
}
__global__ void k_prep_w5(const float* __restrict__ w5) {
    int idx = blockIdx.x * 256 + threadIdx.x;            // 4194304
    int n = idx >> 13, k = idx & 8191;
    int c = k >> 7, p = k & 127;
    float v = w5[idx];
    __half h = __float2half_rn(v);
    int d = n * 8192 + p * 64 + c;
    g_w5h[d] = h; g_w5l[d] = __float2half_rn(v - __half2float(h));
}
__global__ void k_prep_w67(const float* __restrict__ w6, const float* __restrict__ w7) {
    int idx = blockIdx.x * 256 + threadIdx.x;            // 327680
    if (idx >= 327680) return;
    if (idx < 262144) {
        float v = w6[idx];
        __half h = __float2half_rn(v);
        g_w6h[idx] = h; g_w6l[idx] = __float2half_rn(v - __half2float(h));
    } else {
        int d = idx - 262144;
        float v = w7[d];
        __half h = __float2half_rn(v);
        g_w7h[d] = h; g_w7l[d] = __float2half_rn(v - __half2float(h));
    }
}

// ---------------- conv1: bn0 + conv1 + bn1 + relu -> g_a1h [p][b][c] ----------------
__global__ __launch_bounds__(256) void k_conv1(
    const float* __restrict__ x, const float* __restrict__ bn0,
    const float* __restrict__ w1, const float* __restrict__ b1,
    const float* __restrict__ bn1)
{
    __shared__ float h0s[180];
    __shared__ float w1s[576];
    __shared__ float s1s[64], t1s[64];
    int b = blockIdx.x, t = threadIdx.x;
    if (t < 180) h0s[t] = 0.f;
    for (int i = t; i < 576; i += 256) w1s[i] = w1[i];
    if (t < 64) {
        float s = bn1[t] * rsqrtf(bn1[192 + t] + EPSF);
        s1s[t] = s;
        t1s[t] = bn1[64 + t] - bn1[128 + t] * s + b1[t] * s;
    }
    __syncthreads();
    if (t < 128) {
        float s0 = bn0[0] * rsqrtf(bn0[3] + EPSF);
        float t0 = bn0[1] - bn0[2] * s0;
        int i = t >> 4, j = t & 15;
        h0s[(i + 1) * 18 + (j + 1)] = x[b * 128 + j * 8 + i] * s0 + t0;
    }
    __syncthreads();
    for (int idx = t; idx < 2048; idx += 256) {
        int p = idx >> 4, o4 = (idx & 15) << 2;
        int i = p >> 4, j = p & 15;
        __half hh[4];
        #pragma unroll
        for (int q = 0; q < 4; q++) {
            int o = o4 + q;
            float acc = 0.f;
            #pragma unroll
            for (int di = 0; di < 3; di++)
                #pragma unroll
                for (int dj = 0; dj < 3; dj++)
                    acc = fmaf(h0s[(i + di) * 18 + (j + dj)], w1s[o * 9 + di * 3 + dj], acc);
            hh[q] = __float2half_rn(fmaxf(fmaf(acc, s1s[o], t1s[o]), 0.f));
        }
        *reinterpret_cast<uint2*>(&g_a1h[(size_t)p * 524288 + (size_t)b * 64 + o4]) =
            make_uint2(packh2(hh[0], hh[1]), packh2(hh[2], hh[3]));
    }
}

// ---------------- fused conv2 + lc3 + lc4 (wmma, A-fp16 x W-hi/lo) ----------------
// grid (128 pixels, 64 btiles of 128), 256 threads (8 warps, warp tile 32x32).
// Per-tap buffer: AH 0 (18432), WH 18432 (9216), WL 27648 (9216) -> 36864. Two buffers.
#define CL_BUF 36864
#define CL_XH  73728
#define CL_W3H 92160
#define CL_W3L 101376
#define CL_W4H 110592
#define CL_W4L 119808
#define CL_BN  129024
#define CL_SMEM 130560
__global__ __launch_bounds__(256) void k_c2lc(
    const float* __restrict__ b2,  const float* __restrict__ bn2,
    const float* __restrict__ bn3, const float* __restrict__ bn4)
{
    extern __shared__ __align__(16) char smem[];
    float*  FB  = reinterpret_cast<float*>(smem);                 // [128][68] f32, aliases buffers
    __half* XH  = reinterpret_cast<__half*>(smem + CL_XH);
    __half* W3H = reinterpret_cast<__half*>(smem + CL_W3H);
    __half* W3L = reinterpret_cast<__half*>(smem + CL_W3L);
    __half* W4H = reinterpret_cast<__half*>(smem + CL_W4H);
    __half* W4L = reinterpret_cast<__half*>(smem + CL_W4L);
    float*  BN  = reinterpret_cast<float*>(smem + CL_BN);

    int p = blockIdx.x, b0 = blockIdx.y * 128, t = threadIdx.x;
    int w = t >> 5, wm = w & 3, wn = w >> 2;
    int i = p >> 4, j = p & 15;

    if (t < 64) {
        float s = bn2[t] * rsqrtf(bn2[192 + t] + EPSF);
        BN[t] = s;       BN[64 + t]  = bn2[64 + t] - bn2[128 + t] * s + b2[t] * s;
        s = bn3[t] * rsqrtf(bn3[192 + t] + EPSF);
        BN[128 + t] = s; BN[192 + t] = bn3[64 + t] - bn3[128 + t] * s;
        s = bn4[t] * rsqrtf(bn4[192 + t] + EPSF);
        BN[256 + t] = s; BN[320 + t] = bn4[64 + t] - bn4[128 + t] * s;
    }

    // lc weights (independent of taps)
    ldta(g_w3h + p * 4096, 64, W3H, t, 256, 64);
    ldta(g_w3l + p * 4096, 64, W3L, t, 256, 64);
    ldta(g_w4h + p * 4096, 64, W4H, t, 256, 64);
    ldta(g_w4l + p * 4096, 64, W4L, t, 256, 64);
    __pipeline_commit();

    int vt[9], nv = 0;
    #pragma unroll
    for (int tap = 0; tap < 9; tap++) {
        int ii = i + tap / 3 - 1, jj = j + tap % 3 - 1;
        if (ii >= 0 && ii < 8 && jj >= 0 && jj < 16) vt[nv++] = tap;
    }

    FragC acc[2][2];
    FragA ah;
    #pragma unroll
    for (int mt = 0; mt < 2; mt++)
        #pragma unroll
        for (int nt = 0; nt < 2; nt++) wmma::fill_fragment(acc[mt][nt], 0.f);

    auto issue = [&](int q, int bf) {
        int tap = vt[q];
        int pp = (i + tap / 3 - 1) * 16 + (j + tap % 3 - 1);
        char* B = smem + bf * CL_BUF;
        ldta(g_a1h + (size_t)pp * 524288 + (size_t)b0 * 64, 64,
             reinterpret_cast<__half*>(B), t, 256, 128);
        ldta(g_w2th + tap * 4096, 64, reinterpret_cast<__half*>(B + 18432), t, 256, 64);
        ldta(g_w2tl + tap * 4096, 64, reinterpret_cast<__half*>(B + 27648), t, 256, 64);
        __pipeline_commit();
    };

    issue(0, 0);
    for (int q = 0; q < nv; q++) {
        if (q + 1 < nv) issue(q + 1, (q + 1) & 1);
        __pipeline_wait_prior((q + 1 < nv) ? 1 : 0);
        __syncthreads();
        char* B = smem + (q & 1) * CL_BUF;
        __half* AH = reinterpret_cast<__half*>(B);
        __half* WH = reinterpret_cast<__half*>(B + 18432);
        __half* WL = reinterpret_cast<__half*>(B + 27648);
        #pragma unroll
        for (int ks = 0; ks < 4; ks++) {
            FragB bhf[2], blf[2];
            #pragma unroll
            for (int nt = 0; nt < 2; nt++) {
                wmma::load_matrix_sync(bhf[nt], &WH[(wn * 32 + nt * 16) * 72 + ks * 16], 72);
                wmma::load_matrix_sync(blf[nt], &WL[(wn * 32 + nt * 16) * 72 + ks * 16], 72);
            }
            #pragma unroll
            for (int mt = 0; mt < 2; mt++) {
                wmma::load_matrix_sync(ah, &AH[(wm * 32 + mt * 16) * 72 + ks * 16], 72);
                #pragma unroll
                for (int nt = 0; nt < 2; nt++) {
                    wmma::mma_sync(acc[mt][nt], ah, bhf[nt], acc[mt][nt]);
                    wmma::mma_sync(acc[mt][nt], ah, blf[nt], acc[mt][nt]);
                }
            }
        }
        __syncthreads();
    }

    // ---- conv2 epilogue -> XH ----
    #pragma unroll
    for (int mt = 0; mt < 2; mt++)
        #pragma unroll
        for (int nt = 0; nt < 2; nt++)
            wmma::store_matrix_sync(&FB[(wm * 32 + mt * 16) * 68 + wn * 32 + nt * 16],
                                    acc[mt][nt], 68, wmma::mem_row_major);
    __syncthreads();
    for (int q = 0; q < 8; q++) {
        int g = t + q * 256;
        int r = g >> 4, c4 = (g & 15) * 4;
        float4 v = *reinterpret_cast<float4*>(&FB[r * 68 + c4]);
        float* vp = &v.x;
        __half hh[4];
        #pragma unroll
        for (int qq = 0; qq < 4; qq++)
            hh[qq] = __float2half_rn(fmaxf(fmaf(vp[qq], BN[c4 + qq], BN[64 + c4 + qq]), 0.f));
        *reinterpret_cast<uint32_t*>(&XH[r * 72 + c4])     = packh2(hh[0], hh[1]);
        *reinterpret_cast<uint32_t*>(&XH[r * 72 + c4 + 2]) = packh2(hh[2], hh[3]);
    }
    __syncthreads();

    // ---- lc3 ----
    #pragma unroll
    for (int mt = 0; mt < 2; mt++)
        #pragma unroll
        for (int nt = 0; nt < 2; nt++) wmma::fill_fragment(acc[mt][nt], 0.f);
    #pragma unroll
    for (int ks = 0; ks < 4; ks++) {
        FragB bhf[2], blf[2];
        #pragma unroll
        for (int nt = 0; nt < 2; nt++) {
            wmma::load_matrix_sync(bhf[nt], &W3H[(wn * 32 + nt * 16) * 72 + ks * 16], 72);
            wmma::load_matrix_sync(blf[nt], &W3L[(wn * 32 + nt * 16) * 72 + ks * 16], 72);
        }
        #pragma unroll
        for (int mt = 0; mt < 2; mt++) {
            wmma::load_matrix_sync(ah, &XH[(wm * 32 + mt * 16) * 72 + ks * 16], 72);
            #pragma unroll
            for (int nt = 0; nt < 2; nt++) {
                wmma::mma_sync(acc[mt][nt], ah, bhf[nt], acc[mt][nt]);
                wmma::mma_sync(acc[mt][nt], ah, blf[nt], acc[mt][nt]);
            }
        }
    }
    __syncthreads();   // XH reads done before overwrite
    #pragma unroll
    for (int mt = 0; mt < 2; mt++)
        #pragma unroll
        for (int nt = 0; nt < 2; nt++)
            wmma::store_matrix_sync(&FB[(wm * 32 + mt * 16) * 68 + wn * 32 + nt * 16],
                                    acc[mt][nt], 68, wmma::mem_row_major);
    __syncthreads();
    for (int q = 0; q < 8; q++) {
        int g = t + q * 256;
        int r = g >> 4, c4 = (g & 15) * 4;
        float4 v = *reinterpret_cast<float4*>(&FB[r * 68 + c4]);
        float* vp = &v.x;
        __half hh[4];
        #pragma unroll
        for (int qq = 0; qq < 4; qq++)
            hh[qq] = __float2half_rn(fmaxf(fmaf(vp[qq], BN[128 + c4 + qq], BN[192 + c4 + qq]), 0.f));
        *reinterpret_cast<uint32_t*>(&XH[r * 72 + c4])     = packh2(hh[0], hh[1]);
        *reinterpret_cast<uint32_t*>(&XH[r * 72 + c4 + 2]) = packh2(hh[2], hh[3]);
    }
    __syncthreads();

    // ---- lc4 ----
    #pragma unroll
    for (int mt = 0; mt < 2; mt++)
        #pragma unroll
        for (int nt = 0; nt < 2; nt++) wmma::fill_fragment(acc[mt][nt], 0.f);
    #pragma unroll
    for (int ks = 0; ks < 4; ks++) {
        FragB bhf[2], blf[2];
        #pragma unroll
        for (int nt = 0; nt < 2; nt++) {
            wmma::load_matrix_sync(bhf[nt], &W4H[(wn * 32 + nt * 16) * 72 + ks * 16], 72);
            wmma::load_matrix_sync(blf[nt], &W4L[(wn * 32 + nt * 16) * 72 + ks * 16], 72);
        }
        #pragma unroll
        for (int mt = 0; mt < 2; mt++) {
            wmma::load_matrix_sync(ah, &XH[(wm * 32 + mt * 16) * 72 + ks * 16], 72);
            #pragma unroll
            for (int nt = 0; nt < 2; nt++) {
                wmma::mma_sync(acc[mt][nt], ah, bhf[nt], acc[mt][nt]);
                wmma::mma_sync(acc[mt][nt], ah, blf[nt], acc[mt][nt]);
            }
        }
    }
    __syncthreads();
    #pragma unroll
    for (int mt = 0; mt < 2; mt++)
        #pragma unroll
        for (int nt = 0; nt < 2; nt++)
            wmma::store_matrix_sync(&FB[(wm * 32 + mt * 16) * 68 + wn * 32 + nt * 16],
                                    acc[mt][nt], 68, wmma::mem_row_major);
    __syncthreads();
    for (int q = 0; q < 8; q++) {
        int g = t + q * 256;
        int r = g >> 4, c4 = (g & 15) * 4;
        float4 v = *reinterpret_cast<float4*>(&FB[r * 68 + c4]);
        float* vp = &v.x;
        __half hh[4];
        #pragma unroll
        for (int qq = 0; qq < 4; qq++)
            hh[qq] = __float2half_rn(fmaxf(fmaf(vp[qq], BN[256 + c4 + qq], BN[320 + c4 + qq]), 0.f));
        *reinterpret_cast<uint2*>(&g_a4h[(size_t)(b0 + r) * 8192 + p * 64 + c4]) =
            make_uint2(packh2(hh[0], hh[1]), packh2(hh[2], hh[3]));
    }
}

// ---------------- generic wmma fc layer (fc5/fc6/fc7), A-fp16 x W-hi/lo ----------------
// sel: 0 = fc5 (a4->a5, K=8192), 1 = fc6 (a5->a6, K=512), 2 = fc7 (a6->a7 f32, K=512, N=128)
// Per-chunk buffer: AH 0 (18432), WH 18432, WL 36864 -> 55296. Two buffers.
#define FC_BUF 55296
#define FC_SMEM 110592
__global__ __launch_bounds__(512) void k_fcw(int sel, const float* __restrict__ bias,
                                             const float* __restrict__ bn)
{
    extern __shared__ __align__(16) char smem[];
    float* FB = reinterpret_cast<float*>(smem);             // [128][132]

    const __half *Ah, *Wh, *Wl;
    __half *Oh = nullptr;
    float *Of = nullptr;
    int K;
    if (sel == 0)      { Ah = g_a4h; Wh = g_w5h; Wl = g_w5l; Oh = g_a5h; K = 8192; }
    else if (sel == 1) { Ah = g_a5h; Wh = g_w6h; Wl = g_w6l; Oh = g_a6h; K = 512; }
    else               { Ah = g_a6h; Wh = g_w7h; Wl = g_w7l; Of = g_a7; K = 512; }
    int N = (sel == 2) ? 128 : 512;
    int nch = K >> 6;

    int b0 = blockIdx.x * 128, nb = blockIdx.y * 128, t = threadIdx.x;
    int w = t >> 5, wm = w & 3, wn = w >> 2;                 // 16 warps: 4x4 of 32x32

    FragC acc[2][2];
    FragA ah;
    #pragma unroll
    for (int mt = 0; mt < 2; mt++)
        #pragma unroll
        for (int nt = 0; nt < 2; nt++) wmma::fill_fragment(acc[mt][nt], 0.f);

    auto issue = [&](int k, int bf) {
        char* B = smem + bf * FC_BUF;
        ldta(Ah + (size_t)b0 * K + k * 64, K, reinterpret_cast<__half*>(B), t, 512, 128);
        ldta(Wh + (size_t)nb * K + k * 64, K, reinterpret_cast<__half*>(B + 18432), t, 512, 128);
        ldta(Wl + (size_t)nb * K + k * 64, K, reinterpret_cast<__half*>(B + 36864), t, 512, 128);
        __pipeline_commit();
    };

    issue(0, 0);
    for (int k = 0; k < nch; k++) {
        if (k + 1 < nch) issue(k + 1, (k + 1) & 1);
        __pipeline_wait_prior((k + 1 < nch) ? 1 : 0);
        __syncthreads();
        char* B = smem + (k & 1) * FC_BUF;
        __half* AH = reinterpret_cast<__half*>(B);
        __half* WH = reinterpret_cast<__half*>(B + 18432);
        __half* WL = reinterpret_cast<__half*>(B + 36864);
        #pragma unroll
        for (int ks = 0; ks < 4; ks++) {
            FragB bhf[2], blf[2];
            #pragma unroll
            for (int nt = 0; nt < 2; nt++) {
                wmma::load_matrix_sync(bhf[nt], &WH[(wn * 32 + nt * 16) * 72 + ks * 16], 72);
                wmma::load_matrix_sync(blf[nt], &WL[(wn * 32 + nt * 16) * 72 + ks * 16], 72);
            }
            #pragma unroll
            for (int mt = 0; mt < 2; mt++) {
                wmma::load_matrix_sync(ah, &AH[(wm * 32 + mt * 16) * 72 + ks * 16], 72);
                #pragma unroll
                for (int nt = 0; nt < 2; nt++) {
                    wmma::mma_sync(acc[mt][nt], ah, bhf[nt], acc[mt][nt]);
                    wmma::mma_sync(acc[mt][nt], ah, blf[nt], acc[mt][nt]);
                }
            }
        }
        __syncthreads();
    }
    #pragma unroll
    for (int mt = 0; mt < 2; mt++)
        #pragma unroll
        for (int nt = 0; nt < 2; nt++)
            wmma::store_matrix_sync(&FB[(wm * 32 + mt * 16) * 132 + wn * 32 + nt * 16],
                                    acc[mt][nt], 132, wmma::mem_row_major);
    __syncthreads();
    float s = bn[0] * rsqrtf(bn[3] + EPSF);
    float tt = bn[1] - bn[2] * s;
    for (int q = 0; q < 8; q++) {
        int g = t + q * 512;
        int r = g >> 5, c4 = (g & 31) * 4;
        float4 v = *reinterpret_cast<float4*>(&FB[r * 132 + c4]);
        float* vp = &v.x;
        float z[4];
        #pragma unroll
        for (int qq = 0; qq < 4; qq++)
            z[qq] = fmaxf(fmaf(vp[qq] + __ldg(&bias[nb + c4 + qq]), s, tt), 0.f);
        if (Of) {
            *reinterpret_cast<float4*>(&Of[(size_t)(b0 + r) * N + nb + c4]) =
                make_float4(z[0], z[1], z[2], z[3]);
        } else {
            __half hh[4];
            #pragma unroll
            for (int qq = 0; qq < 4; qq++) hh[qq] = __float2half_rn(z[qq]);
            *reinterpret_cast<uint2*>(&Oh[(size_t)(b0 + r) * 512 + nb + c4]) =
                make_uint2(packh2(hh[0], hh[1]), packh2(hh[2], hh[3]));
        }
    }
}

// ---------------- fc8: (B,128) @ (8,128)^T + b8 -> d_out ----------------
__global__ __launch_bounds__(256) void k_fc8(const float* __restrict__ w8,
                                             const float* __restrict__ b8,
                                             float* __restrict__ out)
{
    int t = threadIdx.x;
    int b = blockIdx.x * 32 + (t >> 3), n = t & 7;
    const float* ar = &g_a7[b * 128];
    const float* wr = &w8[n * 128];
    float acc = 0.f;
    #pragma unroll 8
    for (int k = 0; k < 128; k++) acc = fmaf(ar[k], wr[k], acc);
    out[b * 8 + n] = acc + b8[n];
}

// ---------------- launch ----------------
extern "C" void kernel_launch(void* const* d_in, const int* in_sizes, int n_in,
                              void* d_out, int out_size)
{
    const float* x   = (const float*)d_in[0];
    const float* bn0 = (const float*)d_in[1];
    const float* w1  = (const float*)d_in[2];
    const float* b1  = (const float*)d_in[3];
    const float* bn1 = (const float*)d_in[4];
    const float* w2  = (const float*)d_in[5];
    const float* b2  = (const float*)d_in[6];
    const float* bn2 = (const float*)d_in[7];
    const float* w3  = (const float*)d_in[8];
    const float* bn3 = (const float*)d_in[9];
    const float* w4  = (const float*)d_in[10];
    const float* bn4 = (const float*)d_in[11];
    const float* w5  = (const float*)d_in[12];
    const float* b5  = (const float*)d_in[13];
    const float* bn5 = (const float*)d_in[14];
    const float* w6  = (const float*)d_in[15];
    const float* b6  = (const float*)d_in[16];
    const float* bn6 = (const float*)d_in[17];
    const float* w7  = (const float*)d_in[18];
    const float* b7  = (const float*)d_in[19];
    const float* bn7 = (const float*)d_in[20];
    const float* w8  = (const float*)d_in[21];
    const float* b8  = (const float*)d_in[22];
    float* out = (float*)d_out;

    cudaFuncSetAttribute(k_c2lc, cudaFuncAttributeMaxDynamicSharedMemorySize, CL_SMEM);
    cudaFuncSetAttribute(k_fcw,  cudaFuncAttributeMaxDynamicSharedMemorySize, FC_SMEM);

    k_prep_w2 <<<144,   256>>>(w2);
    k_prep_w34<<<4096,  256>>>(w3, w4);
    k_prep_w5 <<<16384, 256>>>(w5);
    k_prep_w67<<<1280,  256>>>(w6, w7);

    k_conv1<<<8192, 256>>>(x, bn0, w1, b1, bn1);
    k_c2lc<<<dim3(128, 64), 256, CL_SMEM>>>(b2, bn2, bn3, bn4);
    k_fcw<<<dim3(64, 4), 512, FC_SMEM>>>(0, b5, bn5);
    k_fcw<<<dim3(64, 4), 512, FC_SMEM>>>(1, b6, bn6);
    k_fcw<<<dim3(64, 1), 512, FC_SMEM>>>(2, b7, bn7);
    k_fc8<<<256, 256>>>(w8, b8, out);
}

// round 15
// speedup vs baseline: 7.1396x; 1.6396x over previous
#include <cuda_runtime.h>
#include <cuda_fp16.h>
#include <cuda_pipeline.h>
#include <mma.h>
#include <cstdint>
using namespace nvcuda;
#define EPSF 1e-5f
// B=8192, C=64, H=8, W=16, P=128, F5=8192

// ---------------- scratch ----------------
__device__ __half g_w2t[36864];                         // conv2 w [tap][o][c] fp16
__device__ __half g_w3[524288];                         // lc3 w [p][o][c] fp16
__device__ __half g_w4[524288];                         // lc4 w [p][o][c] fp16
__device__ __half g_w5[4194304];                        // fc5 w [n][p*64+c] fp16
__device__ __half g_w6[262144];                         // fc6 w [n][k] fp16
__device__ __half g_w7[65536];                          // fc7 w [n][k] fp16
__device__ __half g_a1[67108864];                       // conv1 out [p][b][c] fp16
__device__ __half g_a4[67108864];                       // lc4 out [b][p*64+c] fp16
__device__ __half g_a5[4194304];                        // fc5 out fp16
__device__ __half g_a6[4194304];                        // fc6 out fp16
__device__ float  g_a7[1048576];                        // fc7 out f32

__device__ __forceinline__ uint32_t packh2(__half a, __half b) {
    __half2 h = __halves2half2(a, b);
    return *reinterpret_cast<uint32_t*>(&h);
}
// async load [rows x 64 halves] tile into smem rows of 72 halves (pad)
__device__ __forceinline__ void ldta(const __half* __restrict__ src, size_t rowStride,
                                     __half* dst, int t, int nt, int rows) {
    for (int i = t; i < rows * 8; i += nt) {
        int r = i >> 3, c = i & 7;
        __pipeline_memcpy_async(&dst[r * 72 + c * 8], &src[(size_t)r * rowStride + c * 8], 16);
    }
}

typedef wmma::fragment<wmma::matrix_a, 16,16,16, __half, wmma::row_major> FragA;
typedef wmma::fragment<wmma::matrix_b, 16,16,16, __half, wmma::col_major> FragB;
typedef wmma::fragment<wmma::accumulator, 16,16,16, float> FragC;

// ---------------- weight prep ----------------
__global__ void k_prep_w2(const float* __restrict__ w2) {
    int idx = blockIdx.x * 256 + threadIdx.x;
    if (idx >= 36864) return;
    int o = idx / 576, r = idx % 576;                    // in: [o][c][tap]
    int c = r / 9, tap = r % 9;
    g_w2t[tap * 4096 + o * 64 + c] = __float2half_rn(w2[idx]);
}
__global__ void k_prep_w34(const float* __restrict__ w3, const float* __restrict__ w4) {
    int idx = blockIdx.x * 256 + threadIdx.x;            // 1048576
    int sel = idx >> 19, i = idx & 524287;
    int o = i >> 13, c = (i >> 7) & 63, p = i & 127;
    __half h = __float2half_rn(sel ? w4[i] : w3[i]);
    int d = p * 4096 + o * 64 + c;
    if (sel) g_w4[d] = h; else g_w3[d] = h;
}
__global__ void k_prep_w5(const float* __restrict__ w5) {
    int idx = blockIdx.x * 256 + threadIdx.x;            // 4194304
    int n = idx >> 13, k = idx & 8191;
    int c = k >> 7, p = k & 127;
    g_w5[n * 8192 + p * 64 + c] = __float2half_rn(w5[idx]);
}
__global__ void k_prep_w67(const float* __restrict__ w6, const float* __restrict__ w7) {
    int idx = blockIdx.x * 256 + threadIdx.x;            // 327680
    if (idx >= 327680) return;
    if (idx < 262144) g_w6[idx] = __float2half_rn(w6[idx]);
    else { int d = idx - 262144; g_w7[d] = __float2half_rn(w7[d]); }
}

// ---------------- conv1: bn0 + conv1 + bn1 + relu -> g_a1 [p][b][c] ----------------
__global__ __launch_bounds__(256) void k_conv1(
    const float* __restrict__ x, const float* __restrict__ bn0,
    const float* __restrict__ w1, const float* __restrict__ b1,
    const float* __restrict__ bn1)
{
    __shared__ float h0s[180];
    __shared__ float w1s[576];
    __shared__ float s1s[64], t1s[64];
    int b = blockIdx.x, t = threadIdx.x;
    if (t < 180) h0s[t] = 0.f;
    for (int i = t; i < 576; i += 256) w1s[i] = w1[i];
    if (t < 64) {
        float s = bn1[t] * rsqrtf(bn1[192 + t] + EPSF);
        s1s[t] = s;
        t1s[t] = bn1[64 + t] - bn1[128 + t] * s + b1[t] * s;
    }
    __syncthreads();
    if (t < 128) {
        float s0 = bn0[0] * rsqrtf(bn0[3] + EPSF);
        float t0 = bn0[1] - bn0[2] * s0;
        int i = t >> 4, j = t & 15;
        h0s[(i + 1) * 18 + (j + 1)] = x[b * 128 + j * 8 + i] * s0 + t0;
    }
    __syncthreads();
    for (int idx = t; idx < 2048; idx += 256) {
        int p = idx >> 4, o4 = (idx & 15) << 2;
        int i = p >> 4, j = p & 15;
        __half hh[4];
        #pragma unroll
        for (int q = 0; q < 4; q++) {
            int o = o4 + q;
            float acc = 0.f;
            #pragma unroll
            for (int di = 0; di < 3; di++)
                #pragma unroll
                for (int dj = 0; dj < 3; dj++)
                    acc = fmaf(h0s[(i + di) * 18 + (j + dj)], w1s[o * 9 + di * 3 + dj], acc);
            hh[q] = __float2half_rn(fmaxf(fmaf(acc, s1s[o], t1s[o]), 0.f));
        }
        *reinterpret_cast<uint2*>(&g_a1[(size_t)p * 524288 + (size_t)b * 64 + o4]) =
            make_uint2(packh2(hh[0], hh[1]), packh2(hh[2], hh[3]));
    }
}

// ---------------- fused conv2 + lc3 + lc4 (wmma fp16) ----------------
// grid (128 pixels, 64 btiles of 128), 256 threads (8 warps, warp tile 32x32).
// Per-tap buffer: A 0 (18432), W 18432 (9216) -> 27648. Two buffers.
#define CL_BUF 27648
#define CL_XH  55296
#define CL_W3  73728
#define CL_W4  82944
#define CL_BN  92160
#define CL_SMEM 93696
__global__ __launch_bounds__(256) void k_c2lc(
    const float* __restrict__ b2,  const float* __restrict__ bn2,
    const float* __restrict__ bn3, const float* __restrict__ bn4)
{
    extern __shared__ __align__(16) char smem[];
    float*  FB = reinterpret_cast<float*>(smem);                  // [128][68] f32, aliases buffers
    __half* XH = reinterpret_cast<__half*>(smem + CL_XH);
    __half* W3 = reinterpret_cast<__half*>(smem + CL_W3);
    __half* W4 = reinterpret_cast<__half*>(smem + CL_W4);
    float*  BN = reinterpret_cast<float*>(smem + CL_BN);

    int p = blockIdx.x, b0 = blockIdx.y * 128, t = threadIdx.x;
    int w = t >> 5, wm = w & 3, wn = w >> 2;
    int i = p >> 4, j = p & 15;

    if (t < 64) {
        float s = bn2[t] * rsqrtf(bn2[192 + t] + EPSF);
        BN[t] = s;       BN[64 + t]  = bn2[64 + t] - bn2[128 + t] * s + b2[t] * s;
        s = bn3[t] * rsqrtf(bn3[192 + t] + EPSF);
        BN[128 + t] = s; BN[192 + t] = bn3[64 + t] - bn3[128 + t] * s;
        s = bn4[t] * rsqrtf(bn4[192 + t] + EPSF);
        BN[256 + t] = s; BN[320 + t] = bn4[64 + t] - bn4[128 + t] * s;
    }

    ldta(g_w3 + p * 4096, 64, W3, t, 256, 64);
    ldta(g_w4 + p * 4096, 64, W4, t, 256, 64);
    __pipeline_commit();

    int vt[9], nv = 0;
    #pragma unroll
    for (int tap = 0; tap < 9; tap++) {
        int ii = i + tap / 3 - 1, jj = j + tap % 3 - 1;
        if (ii >= 0 && ii < 8 && jj >= 0 && jj < 16) vt[nv++] = tap;
    }

    FragC acc[2][2];
    FragA ah;
    #pragma unroll
    for (int mt = 0; mt < 2; mt++)
        #pragma unroll
        for (int nt = 0; nt < 2; nt++) wmma::fill_fragment(acc[mt][nt], 0.f);

    auto issue = [&](int q, int bf) {
        int tap = vt[q];
        int pp = (i + tap / 3 - 1) * 16 + (j + tap % 3 - 1);
        char* B = smem + bf * CL_BUF;
        ldta(g_a1 + (size_t)pp * 524288 + (size_t)b0 * 64, 64,
             reinterpret_cast<__half*>(B), t, 256, 128);
        ldta(g_w2t + tap * 4096, 64, reinterpret_cast<__half*>(B + 18432), t, 256, 64);
        __pipeline_commit();
    };

    issue(0, 0);
    for (int q = 0; q < nv; q++) {
        if (q + 1 < nv) issue(q + 1, (q + 1) & 1);
        __pipeline_wait_prior((q + 1 < nv) ? 1 : 0);
        __syncthreads();
        char* B = smem + (q & 1) * CL_BUF;
        __half* AH = reinterpret_cast<__half*>(B);
        __half* WH = reinterpret_cast<__half*>(B + 18432);
        #pragma unroll
        for (int ks = 0; ks < 4; ks++) {
            FragB bhf[2];
            #pragma unroll
            for (int nt = 0; nt < 2; nt++)
                wmma::load_matrix_sync(bhf[nt], &WH[(wn * 32 + nt * 16) * 72 + ks * 16], 72);
            #pragma unroll
            for (int mt = 0; mt < 2; mt++) {
                wmma::load_matrix_sync(ah, &AH[(wm * 32 + mt * 16) * 72 + ks * 16], 72);
                #pragma unroll
                for (int nt = 0; nt < 2; nt++)
                    wmma::mma_sync(acc[mt][nt], ah, bhf[nt], acc[mt][nt]);
            }
        }
        __syncthreads();
    }

    // ---- conv2 epilogue -> XH ----
    #pragma unroll
    for (int mt = 0; mt < 2; mt++)
        #pragma unroll
        for (int nt = 0; nt < 2; nt++)
            wmma::store_matrix_sync(&FB[(wm * 32 + mt * 16) * 68 + wn * 32 + nt * 16],
                                    acc[mt][nt], 68, wmma::mem_row_major);
    __syncthreads();
    for (int q = 0; q < 8; q++) {
        int g = t + q * 256;
        int r = g >> 4, c4 = (g & 15) * 4;
        float4 v = *reinterpret_cast<float4*>(&FB[r * 68 + c4]);
        float* vp = &v.x;
        __half hh[4];
        #pragma unroll
        for (int qq = 0; qq < 4; qq++)
            hh[qq] = __float2half_rn(fmaxf(fmaf(vp[qq], BN[c4 + qq], BN[64 + c4 + qq]), 0.f));
        *reinterpret_cast<uint32_t*>(&XH[r * 72 + c4])     = packh2(hh[0], hh[1]);
        *reinterpret_cast<uint32_t*>(&XH[r * 72 + c4 + 2]) = packh2(hh[2], hh[3]);
    }
    __syncthreads();

    // ---- lc3 ----
    #pragma unroll
    for (int mt = 0; mt < 2; mt++)
        #pragma unroll
        for (int nt = 0; nt < 2; nt++) wmma::fill_fragment(acc[mt][nt], 0.f);
    #pragma unroll
    for (int ks = 0; ks < 4; ks++) {
        FragB bhf[2];
        #pragma unroll
        for (int nt = 0; nt < 2; nt++)
            wmma::load_matrix_sync(bhf[nt], &W3[(wn * 32 + nt * 16) * 72 + ks * 16], 72);
        #pragma unroll
        for (int mt = 0; mt < 2; mt++) {
            wmma::load_matrix_sync(ah, &XH[(wm * 32 + mt * 16) * 72 + ks * 16], 72);
            #pragma unroll
            for (int nt = 0; nt < 2; nt++)
                wmma::mma_sync(acc[mt][nt], ah, bhf[nt], acc[mt][nt]);
        }
    }
    __syncthreads();
    #pragma unroll
    for (int mt = 0; mt < 2; mt++)
        #pragma unroll
        for (int nt = 0; nt < 2; nt++)
            wmma::store_matrix_sync(&FB[(wm * 32 + mt * 16) * 68 + wn * 32 + nt * 16],
                                    acc[mt][nt], 68, wmma::mem_row_major);
    __syncthreads();
    for (int q = 0; q < 8; q++) {
        int g = t + q * 256;
        int r = g >> 4, c4 = (g & 15) * 4;
        float4 v = *reinterpret_cast<float4*>(&FB[r * 68 + c4]);
        float* vp = &v.x;
        __half hh[4];
        #pragma unroll
        for (int qq = 0; qq < 4; qq++)
            hh[qq] = __float2half_rn(fmaxf(fmaf(vp[qq], BN[128 + c4 + qq], BN[192 + c4 + qq]), 0.f));
        *reinterpret_cast<uint32_t*>(&XH[r * 72 + c4])     = packh2(hh[0], hh[1]);
        *reinterpret_cast<uint32_t*>(&XH[r * 72 + c4 + 2]) = packh2(hh[2], hh[3]);
    }
    __syncthreads();

    // ---- lc4 ----
    #pragma unroll
    for (int mt = 0; mt < 2; mt++)
        #pragma unroll
        for (int nt = 0; nt < 2; nt++) wmma::fill_fragment(acc[mt][nt], 0.f);
    #pragma unroll
    for (int ks = 0; ks < 4; ks++) {
        FragB bhf[2];
        #pragma unroll
        for (int nt = 0; nt < 2; nt++)
            wmma::load_matrix_sync(bhf[nt], &W4[(wn * 32 + nt * 16) * 72 + ks * 16], 72);
        #pragma unroll
        for (int mt = 0; mt < 2; mt++) {
            wmma::load_matrix_sync(ah, &XH[(wm * 32 + mt * 16) * 72 + ks * 16], 72);
            #pragma unroll
            for (int nt = 0; nt < 2; nt++)
                wmma::mma_sync(acc[mt][nt], ah, bhf[nt], acc[mt][nt]);
        }
    }
    __syncthreads();
    #pragma unroll
    for (int mt = 0; mt < 2; mt++)
        #pragma unroll
        for (int nt = 0; nt < 2; nt++)
            wmma::store_matrix_sync(&FB[(wm * 32 + mt * 16) * 68 + wn * 32 + nt * 16],
                                    acc[mt][nt], 68, wmma::mem_row_major);
    __syncthreads();
    for (int q = 0; q < 8; q++) {
        int g = t + q * 256;
        int r = g >> 4, c4 = (g & 15) * 4;
        float4 v = *reinterpret_cast<float4*>(&FB[r * 68 + c4]);
        float* vp = &v.x;
        __half hh[4];
        #pragma unroll
        for (int qq = 0; qq < 4; qq++)
            hh[qq] = __float2half_rn(fmaxf(fmaf(vp[qq], BN[256 + c4 + qq], BN[320 + c4 + qq]), 0.f));
        *reinterpret_cast<uint2*>(&g_a4[(size_t)(b0 + r) * 8192 + p * 64 + c4]) =
            make_uint2(packh2(hh[0], hh[1]), packh2(hh[2], hh[3]));
    }
}

// ---------------- generic wmma fc layer (fc5/fc6/fc7), pure fp16 ----------------
// sel: 0 = fc5 (a4->a5, K=8192), 1 = fc6 (a5->a6, K=512), 2 = fc7 (a6->a7 f32, K=512, N=128)
// Per-chunk buffer: A 0 (18432), W 18432 (18432) -> 36864. Two buffers.
#define FC_BUF 36864
#define FC_SMEM 73728
__global__ __launch_bounds__(512) void k_fcw(int sel, const float* __restrict__ bias,
                                             const float* __restrict__ bn)
{
    extern __shared__ __align__(16) char smem[];
    float* FB = reinterpret_cast<float*>(smem);             // [128][132]

    const __half *Ah, *Wh;
    __half *Oh = nullptr;
    float *Of = nullptr;
    int K;
    if (sel == 0)      { Ah = g_a4; Wh = g_w5; Oh = g_a5; K = 8192; }
    else if (sel == 1) { Ah = g_a5; Wh = g_w6; Oh = g_a6; K = 512; }
    else               { Ah = g_a6; Wh = g_w7; Of = g_a7; K = 512; }
    int N = (sel == 2) ? 128 : 512;
    int nch = K >> 6;

    int b0 = blockIdx.x * 128, nb = blockIdx.y * 128, t = threadIdx.x;
    int w = t >> 5, wm = w & 3, wn = w >> 2;                 // 16 warps: 4x4 of 32x32

    FragC acc[2][2];
    FragA ah;
    #pragma unroll
    for (int mt = 0; mt < 2; mt++)
        #pragma unroll
        for (int nt = 0; nt < 2; nt++) wmma::fill_fragment(acc[mt][nt], 0.f);

    auto issue = [&](int k, int bf) {
        char* B = smem + bf * FC_BUF;
        ldta(Ah + (size_t)b0 * K + k * 64, K, reinterpret_cast<__half*>(B), t, 512, 128);
        ldta(Wh + (size_t)nb * K + k * 64, K, reinterpret_cast<__half*>(B + 18432), t, 512, 128);
        __pipeline_commit();
    };

    issue(0, 0);
    for (int k = 0; k < nch; k++) {
        if (k + 1 < nch) issue(k + 1, (k + 1) & 1);
        __pipeline_wait_prior((k + 1 < nch) ? 1 : 0);
        __syncthreads();
        char* B = smem + (k & 1) * FC_BUF;
        __half* AH = reinterpret_cast<__half*>(B);
        __half* WH = reinterpret_cast<__half*>(B + 18432);
        #pragma unroll
        for (int ks = 0; ks < 4; ks++) {
            FragB bhf[2];
            #pragma unroll
            for (int nt = 0; nt < 2; nt++)
                wmma::load_matrix_sync(bhf[nt], &WH[(wn * 32 + nt * 16) * 72 + ks * 16], 72);
            #pragma unroll
            for (int mt = 0; mt < 2; mt++) {
                wmma::load_matrix_sync(ah, &AH[(wm * 32 + mt * 16) * 72 + ks * 16], 72);
                #pragma unroll
                for (int nt = 0; nt < 2; nt++)
                    wmma::mma_sync(acc[mt][nt], ah, bhf[nt], acc[mt][nt]);
            }
        }
        __syncthreads();
    }
    #pragma unroll
    for (int mt = 0; mt < 2; mt++)
        #pragma unroll
        for (int nt = 0; nt < 2; nt++)
            wmma::store_matrix_sync(&FB[(wm * 32 + mt * 16) * 132 + wn * 32 + nt * 16],
                                    acc[mt][nt], 132, wmma::mem_row_major);
    __syncthreads();
    float s = bn[0] * rsqrtf(bn[3] + EPSF);
    float tt = bn[1] - bn[2] * s;
    for (int q = 0; q < 8; q++) {
        int g = t + q * 512;
        int r = g >> 5, c4 = (g & 31) * 4;
        float4 v = *reinterpret_cast<float4*>(&FB[r * 132 + c4]);
        float* vp = &v.x;
        float z[4];
        #pragma unroll
        for (int qq = 0; qq < 4; qq++)
            z[qq] = fmaxf(fmaf(vp[qq] + __ldg(&bias[nb + c4 + qq]), s, tt), 0.f);
        if (Of) {
            *reinterpret_cast<float4*>(&Of[(size_t)(b0 + r) * N + nb + c4]) =
                make_float4(z[0], z[1], z[2], z[3]);
        } else {
            __half hh[4];
            #pragma unroll
            for (int qq = 0; qq < 4; qq++) hh[qq] = __float2half_rn(z[qq]);
            *reinterpret_cast<uint2*>(&Oh[(size_t)(b0 + r) * 512 + nb + c4]) =
                make_uint2(packh2(hh[0], hh[1]), packh2(hh[2], hh[3]));
        }
    }
}

// ---------------- fc8: (B,128) @ (8,128)^T + b8 -> d_out ----------------
__global__ __launch_bounds__(256) void k_fc8(const float* __restrict__ w8,
                                             const float* __restrict__ b8,
                                             float* __restrict__ out)
{
    int t = threadIdx.x;
    int b = blockIdx.x * 32 + (t >> 3), n = t & 7;
    const float* ar = &g_a7[b * 128];
    const float* wr = &w8[n * 128];
    float acc = 0.f;
    #pragma unroll 8
    for (int k = 0; k < 128; k++) acc = fmaf(ar[k], wr[k], acc);
    out[b * 8 + n] = acc + b8[n];
}

// ---------------- launch ----------------
extern "C" void kernel_launch(void* const* d_in, const int* in_sizes, int n_in,
                              void* d_out, int out_size)
{
    const float* x   = (const float*)d_in[0];
    const float* bn0 = (const float*)d_in[1];
    const float* w1  = (const float*)d_in[2];
    const float* b1  = (const float*)d_in[3];
    const float* bn1 = (const float*)d_in[4];
    const float* w2  = (const float*)d_in[5];
    const float* b2  = (const float*)d_in[6];
    const float* bn2 = (const float*)d_in[7];
    const float* w3  = (const float*)d_in[8];
    const float* bn3 = (const float*)d_in[9];
    const float* w4  = (const float*)d_in[10];
    const float* bn4 = (const float*)d_in[11];
    const float* w5  = (const float*)d_in[12];
    const float* b5  = (const float*)d_in[13];
    const float* bn5 = (const float*)d_in[14];
    const float* w6  = (const float*)d_in[15];
    const float* b6  = (const float*)d_in[16];
    const float* bn6 = (const float*)d_in[17];
    const float* w7  = (const float*)d_in[18];
    const float* b7  = (const float*)d_in[19];
    const float* bn7 = (const float*)d_in[20];
    const float* w8  = (const float*)d_in[21];
    const float* b8  = (const float*)d_in[22];
    float* out = (float*)d_out;

    cudaFuncSetAttribute(k_c2lc, cudaFuncAttributeMaxDynamicSharedMemorySize, CL_SMEM);
    cudaFuncSetAttribute(k_fcw,  cudaFuncAttributeMaxDynamicSharedMemorySize, FC_SMEM);

    k_prep_w2 <<<144,   256>>>(w2);
    k_prep_w34<<<4096,  256>>>(w3, w4);
    k_prep_w5 <<<16384, 256>>>(w5);
    k_prep_w67<<<1280,  256>>>(w6, w7);

    k_conv1<<<8192, 256>>>(x, bn0, w1, b1, bn1);
    k_c2lc<<<dim3(128, 64), 256, CL_SMEM>>>(b2, bn2, bn3, bn4);
    k_fcw<<<dim3(64, 4), 512, FC_SMEM>>>(0, b5, bn5);
    k_fcw<<<dim3(64, 4), 512, FC_SMEM>>>(1, b6, bn6);
    k_fcw<<<dim3(64, 1), 512, FC_SMEM>>>(2, b7, bn7);
    k_fc8<<<256, 256>>>(w8, b8, out);
}